// round 14
// baseline (speedup 1.0000x reference)
#include <cuda_runtime.h>
#include <cuda_bf16.h>
#include <cstdint>
#include <cstddef>

// Problem constants (fixed shapes)
#define NMAX 100000
#define EMAX 500000
#define GCNT 512
#define NLAYER 4
#define NTILE ((NMAX + 127) / 128)   // 782

// tcgen05 only exists in the arch-specific (sm_103a) device pass.
#if defined(__CUDA_ARCH__) && defined(__CUDA_ARCH_FEAT_SM103_ALL)
#define HAS_TC 1
#else
#define HAS_TC 0
#endif

// ---------------- device scratch ----------------
__device__ float g_h2 [NMAX * 128];
// aggregated layer input, pre-split bf16 hi/lo, pre-swizzled smem image:
// [tile][chunk(2)][16KB image]  where image[SW128(row*128 + kg*16)]
__device__ uint8_t g_ahi[(size_t)NTILE * 32768];
__device__ uint8_t g_alo[(size_t)NTILE * 32768];
__device__ float g_ssum [256];
__device__ float g_ssq  [256];
__device__ float g_ssum2[128];
__device__ float g_ssq2 [128];
__device__ float g_scale[256];   // used by classifier only now
__device__ float g_shift[256];
__device__ float g_ps [GCNT * 128];
__device__ float g_pmx[GCNT * 128];
__device__ float g_cnt[GCNT];
__device__ float g_z1 [GCNT * 128];
__device__ int   g_i64flag;

// CSR (built once per launch; edges fixed across layers)
__device__ int g_deg [NMAX];
__device__ int g_off [NMAX];
__device__ int g_cur [NMAX];
__device__ int g_csr [EMAX];
__device__ int g_bsum[128];
__device__ int g_bscn[128];

// pre-split weights, B layout: [layer][n(out)][k(in)] bf16, K-major rows
__device__ __nv_bfloat16 g_b1hi[NLAYER * 256 * 128];
__device__ __nv_bfloat16 g_b1lo[NLAYER * 256 * 128];
__device__ __nv_bfloat16 g_b2hi[NLAYER * 128 * 256];
__device__ __nv_bfloat16 g_b2lo[NLAYER * 128 * 256];

// ---------------- PTX helpers ----------------
__device__ __forceinline__ uint32_t smem_u32(const void* p) {
    uint32_t a;
    asm("{ .reg .u64 t; cvta.to.shared.u64 t, %1; cvt.u32.u64 %0, t; }" : "=r"(a) : "l"(p));
    return a;
}
__device__ __forceinline__ uint32_t elect_one() {
    uint32_t p;
    asm volatile("{ .reg .pred p; elect.sync _|p, 0xFFFFFFFF; selp.b32 %0, 1, 0, p; }" : "=r"(p));
    return p;
}
#define SW128(o) ((o) ^ (((o) >> 3) & 0x70))
static __device__ __forceinline__ uint64_t make_desc(uint32_t addr) {
    return ((uint64_t)2 << 61) | ((uint64_t)1 << 46) | ((uint64_t)64 << 32) |
           ((uint64_t)1 << 16) | ((uint64_t)(addr >> 4) & 0x3FFF);
}

#if HAS_TC
__device__ __forceinline__ void mma_bf16_ss(uint32_t d, uint64_t a, uint64_t b,
                                            uint32_t idesc, uint32_t en) {
    asm volatile(
        "{\n\t.reg .pred p;\n\tsetp.ne.u32 p, %4, 0;\n\t"
        "tcgen05.mma.cta_group::1.kind::f16 [%0], %1, %2, %3, {%5, %5, %5, %5}, p;\n\t}"
        :: "r"(d), "l"(a), "l"(b), "r"(idesc), "r"(en), "r"(0u) : "memory");
}
#define TC_ALLOC(sm, n)  asm volatile("tcgen05.alloc.cta_group::1.sync.aligned.shared::cta.b32 [%0], %1;" :: "r"(sm), "r"((uint32_t)(n)) : "memory")
#define TC_DEALLOC(t, n) asm volatile("tcgen05.dealloc.cta_group::1.sync.aligned.b32 %0, %1;" :: "r"(t), "r"((uint32_t)(n)))
#define TC_COMMIT(mb)    asm volatile("tcgen05.commit.cta_group::1.mbarrier::arrive::one.shared::cluster.b64 [%0];" :: "r"(mb) : "memory")
#define TC_FENCE_AFTER() asm volatile("tcgen05.fence::after_thread_sync;" ::: "memory")
#define TC_FENCE_BEFORE() asm volatile("tcgen05.fence::before_thread_sync;" ::: "memory")
#define TC_WAIT_LD()     asm volatile("tcgen05.wait::ld.sync.aligned;" ::: "memory")
#define LDTM32(r, a)                                                            \
    asm volatile("tcgen05.ld.sync.aligned.32x32b.x32.b32 "                      \
        "{%0,%1,%2,%3,%4,%5,%6,%7,%8,%9,%10,%11,%12,%13,%14,%15,"               \
        "%16,%17,%18,%19,%20,%21,%22,%23,%24,%25,%26,%27,%28,%29,%30,%31}, [%32];" \
        : "=r"((r)[0]),"=r"((r)[1]),"=r"((r)[2]),"=r"((r)[3]),                  \
          "=r"((r)[4]),"=r"((r)[5]),"=r"((r)[6]),"=r"((r)[7]),                  \
          "=r"((r)[8]),"=r"((r)[9]),"=r"((r)[10]),"=r"((r)[11]),                \
          "=r"((r)[12]),"=r"((r)[13]),"=r"((r)[14]),"=r"((r)[15]),              \
          "=r"((r)[16]),"=r"((r)[17]),"=r"((r)[18]),"=r"((r)[19]),              \
          "=r"((r)[20]),"=r"((r)[21]),"=r"((r)[22]),"=r"((r)[23]),              \
          "=r"((r)[24]),"=r"((r)[25]),"=r"((r)[26]),"=r"((r)[27]),              \
          "=r"((r)[28]),"=r"((r)[29]),"=r"((r)[30]),"=r"((r)[31])               \
        : "r"(a))
#define MB_WAIT(mb, par) do {                                                   \
    uint32_t _m = (mb), _p = (par), _d;                                         \
    asm volatile("{ .reg .pred p; mbarrier.try_wait.parity.acquire.cta.shared::cta.b64 p, [%1], %2; selp.b32 %0, 1, 0, p; }" \
                 : "=r"(_d) : "r"(_m), "r"(_p) : "memory");                     \
    if (!_d) {                                                                  \
        asm volatile("{ .reg .pred P1; W%=: mbarrier.try_wait.parity.acquire.cta.shared::cta.b64 P1, [%0], %1, 0x989680; @P1 bra.uni D%=; bra.uni W%=; D%=: }" \
                     :: "r"(_m), "r"(_p) : "memory");                           \
    }                                                                           \
} while (0)
#else
__device__ __forceinline__ void mma_bf16_ss(uint32_t, uint64_t, uint64_t, uint32_t, uint32_t) {}
#define TC_ALLOC(sm, n)   ((void)0)
#define TC_DEALLOC(t, n)  ((void)0)
#define TC_COMMIT(mb)     ((void)0)
#define TC_FENCE_AFTER()  ((void)0)
#define TC_FENCE_BEFORE() ((void)0)
#define TC_WAIT_LD()      ((void)0)
#define LDTM32(r, a)      do { _Pragma("unroll") for (int _i = 0; _i < 32; _i++) (r)[_i] = 0u; } while (0)
#define MB_WAIT(mb, par)  ((void)0)
#endif

#define MB_INIT(mb, c)   asm volatile("mbarrier.init.shared.b64 [%0], %1;" :: "r"(mb), "r"((uint32_t)(c)) : "memory")
#define MB_INVAL(mb)     asm volatile("mbarrier.inval.shared.b64 [%0];" :: "r"(mb) : "memory")
#define FENCE_ASYNC()    asm volatile("fence.proxy.async.shared::cta;" ::: "memory")
#define CP_ASYNC16(dst, src) asm volatile("cp.async.ca.shared.global [%0], [%1], 16;" :: "r"(dst), "l"(src) : "memory")
#define CP_COMMIT()      asm volatile("cp.async.commit_group;" ::: "memory")
#define CP_WAIT0()       asm volatile("cp.async.wait_group 0;" ::: "memory")

// ---------------- dtype detection ----------------
__global__ void detect_k(const unsigned int* __restrict__ e) {
    unsigned acc = 0;
    for (int i = 1; i < 128; i += 2) acc |= e[i];
    g_i64flag = (acc == 0u) ? 1 : 0;
}

// ---------------- weight split fp32 -> bf16 hi/lo ----------------
__global__ void wconv_k(const float* __restrict__ W1, const float* __restrict__ W2) {
    int i = blockIdx.x * 256 + threadIdx.x;
    const int tot = NLAYER * 256 * 128;
    if (i >= tot) return;
    int l = i / (256 * 128), rem = i % (256 * 128);
    {
        int n = rem / 128, k = rem % 128;
        float w = W1[l * 32768 + k * 256 + n];
        __nv_bfloat16 h = __float2bfloat16(w);
        g_b1hi[i] = h;
        g_b1lo[i] = __float2bfloat16(w - __bfloat162float(h));
    }
    {
        int n = rem / 256, k = rem % 256;
        float w = W2[l * 32768 + k * 128 + n];
        __nv_bfloat16 h = __float2bfloat16(w);
        g_b2hi[i] = h;
        g_b2lo[i] = __float2bfloat16(w - __bfloat162float(h));
    }
}

// ---------------- zero (grid-stride; covers n + pad tile image) ----------------
__global__ void zero_k(int n, int gx) {
    int tot = (n > GCNT * 128) ? n : GCNT * 128;
    for (int i = blockIdx.x * blockDim.x + threadIdx.x; i < tot;
         i += gridDim.x * blockDim.x) {
        if (i < 256) { g_ssum[i] = 0.f; g_ssq[i] = 0.f; }
        if (i < 128) { g_ssum2[i] = 0.f; g_ssq2[i] = 0.f; }
        if (i < GCNT * 128) { g_ps[i] = 0.f; g_pmx[i] = 0.f; }
        if (i < GCNT) g_cnt[i] = 0.f;
        if (i < n) g_deg[i] = 0;
    }
    // zero the last tile's A-image (pad rows must contribute 0 to raw stats)
    size_t lt = (size_t)(gx - 1) * 32768;
    for (int i = blockIdx.x * blockDim.x + threadIdx.x; i < 32768 / 16;
         i += gridDim.x * blockDim.x) {
        ((uint4*)(g_ahi + lt))[i] = make_uint4(0, 0, 0, 0);
        ((uint4*)(g_alo + lt))[i] = make_uint4(0, 0, 0, 0);
    }
}

// ---------------- CSR build ----------------
__global__ void count_k(const void* __restrict__ ei, long long E) {
    long long e = (long long)blockIdx.x * blockDim.x + threadIdx.x;
    if (e >= E) return;
    int d;
    if (g_i64flag) d = (int)((const long long*)ei)[E + e];
    else           d = ((const int*)ei)[E + e];
    atomicAdd(&g_deg[d], 1);
}

__global__ void scanA_k(int n) {
    __shared__ int sred[256];
    int blk = blockIdx.x, t = threadIdx.x;
    int base = blk * 1024 + t * 4;
    int s = 0;
#pragma unroll
    for (int j = 0; j < 4; j++) {
        int idx = base + j;
        if (idx < n) s += g_deg[idx];
    }
    sred[t] = s;
    __syncthreads();
    for (int o = 128; o > 0; o >>= 1) {
        if (t < o) sred[t] += sred[t + o];
        __syncthreads();
    }
    if (t == 0) g_bsum[blk] = sred[0];
}

__global__ void scanB_k(int nblk) {
    if (threadIdx.x == 0) {
        int run = 0;
        for (int i = 0; i < nblk; i++) { g_bscn[i] = run; run += g_bsum[i]; }
    }
}

__global__ void scanC_k(int n) {
    __shared__ int sth[256];
    int blk = blockIdx.x, t = threadIdx.x;
    int base = blk * 1024 + t * 4;
    int v[4];
    int s = 0;
#pragma unroll
    for (int j = 0; j < 4; j++) {
        int idx = base + j;
        v[j] = (idx < n) ? g_deg[idx] : 0;
        s += v[j];
    }
    sth[t] = s;
    __syncthreads();
    for (int o = 1; o < 256; o <<= 1) {
        int add = (t >= o) ? sth[t - o] : 0;
        __syncthreads();
        sth[t] += add;
        __syncthreads();
    }
    int tpre = (t > 0 ? sth[t - 1] : 0) + g_bscn[blk];
#pragma unroll
    for (int j = 0; j < 4; j++) {
        int idx = base + j;
        if (idx < n) { g_off[idx] = tpre; g_cur[idx] = tpre; }
        tpre += v[j];
    }
}

__global__ void fill_k(const void* __restrict__ ei, long long E) {
    long long e = (long long)blockIdx.x * blockDim.x + threadIdx.x;
    if (e >= E) return;
    int s, d;
    if (g_i64flag) {
        const long long* p = (const long long*)ei;
        s = (int)p[e]; d = (int)p[E + e];
    } else {
        const int* p = (const int*)ei;
        s = p[e]; d = p[E + e];
    }
    int pos = atomicAdd(&g_cur[d], 1);
    if (pos < EMAX) g_csr[pos] = s;
}

__device__ __forceinline__ uint32_t pack_bf16x2(float a, float b) {
    __nv_bfloat162 h = __float22bfloat162_rn(make_float2(a, b));
    return *reinterpret_cast<uint32_t*>(&h);
}

// ---------------- CSR aggregation + bf16 split + swizzled store ----------------
template<bool BN>
__global__ void __launch_bounds__(256) agg_k(
    const float* __restrict__ SRC, const float* __restrict__ epsp, int l, int n,
    const float* __restrict__ gamma, const float* __restrict__ beta, float invM) {
    if (BN && blockIdx.x == 0) {
        g_ssum[threadIdx.x] = 0.f;
        g_ssq[threadIdx.x]  = 0.f;
    }
    int node = (int)(((long long)blockIdx.x * blockDim.x + threadIdx.x) >> 5);
    int lane = threadIdx.x & 31;
    if (node >= n) return;
    float e = 1.0f + epsp[l];

    float sc0, sc1, sc2, sc3, sh0, sh1, sh2, sh3;
    if (BN) {
        int c = lane * 4;
#pragma unroll
        for (int j = 0; j < 4; j++) {
            float m   = g_ssum2[c + j] * invM;
            float var = g_ssq2[c + j] * invM - m * m;
            float sc  = gamma[c + j] * rsqrtf(var + 1e-5f);
            float sh  = beta[c + j] - m * sc;
            if (j == 0) { sc0 = sc; sh0 = sh; }
            else if (j == 1) { sc1 = sc; sh1 = sh; }
            else if (j == 2) { sc2 = sc; sh2 = sh; }
            else { sc3 = sc; sh3 = sh; }
        }
    }
#define FBN(v)                                                                   \
    if (BN) {                                                                    \
        v.x = fmaxf(fmaf(v.x, sc0, sh0), 0.f);                                   \
        v.y = fmaxf(fmaf(v.y, sc1, sh1), 0.f);                                   \
        v.z = fmaxf(fmaf(v.z, sc2, sh2), 0.f);                                   \
        v.w = fmaxf(fmaf(v.w, sc3, sh3), 0.f);                                   \
    }

    int beg = g_off[node];
    int deg = g_deg[node];

    float4 self = ((const float4*)SRC)[(size_t)node * 32 + lane];
    FBN(self);
    float4 a0 = make_float4(self.x * e, self.y * e, self.z * e, self.w * e);
    float4 a1 = make_float4(0.f, 0.f, 0.f, 0.f);
    float4 a2 = make_float4(0.f, 0.f, 0.f, 0.f);
    float4 a3 = make_float4(0.f, 0.f, 0.f, 0.f);

    int i = 0;
    for (; i + 4 <= deg; i += 4) {
        int s0 = g_csr[beg + i];
        int s1 = g_csr[beg + i + 1];
        int s2 = g_csr[beg + i + 2];
        int s3 = g_csr[beg + i + 3];
        float4 v0 = ((const float4*)SRC)[(size_t)s0 * 32 + lane];
        float4 v1 = ((const float4*)SRC)[(size_t)s1 * 32 + lane];
        float4 v2 = ((const float4*)SRC)[(size_t)s2 * 32 + lane];
        float4 v3 = ((const float4*)SRC)[(size_t)s3 * 32 + lane];
        FBN(v0); FBN(v1); FBN(v2); FBN(v3);
        a0.x += v0.x; a0.y += v0.y; a0.z += v0.z; a0.w += v0.w;
        a1.x += v1.x; a1.y += v1.y; a1.z += v1.z; a1.w += v1.w;
        a2.x += v2.x; a2.y += v2.y; a2.z += v2.z; a2.w += v2.w;
        a3.x += v3.x; a3.y += v3.y; a3.z += v3.z; a3.w += v3.w;
    }
    if (i < deg) {
        int rem = deg - i;
        int s0 = g_csr[beg + i];
        int s1 = g_csr[beg + ((rem > 1) ? i + 1 : i)];
        int s2 = g_csr[beg + ((rem > 2) ? i + 2 : i)];
        float4 v0 = ((const float4*)SRC)[(size_t)s0 * 32 + lane];
        float4 v1 = ((const float4*)SRC)[(size_t)s1 * 32 + lane];
        float4 v2 = ((const float4*)SRC)[(size_t)s2 * 32 + lane];
        FBN(v0); FBN(v1); FBN(v2);
        a1.x += v0.x; a1.y += v0.y; a1.z += v0.z; a1.w += v0.w;
        if (rem > 1) { a2.x += v1.x; a2.y += v1.y; a2.z += v1.z; a2.w += v1.w; }
        if (rem > 2) { a3.x += v2.x; a3.y += v2.y; a3.z += v2.z; a3.w += v2.w; }
    }
#undef FBN
    float4 r;
    r.x = (a0.x + a1.x) + (a2.x + a3.x);
    r.y = (a0.y + a1.y) + (a2.y + a3.y);
    r.z = (a0.z + a1.z) + (a2.z + a3.z);
    r.w = (a0.w + a1.w) + (a2.w + a3.w);

    uint32_t h0 = pack_bf16x2(r.x, r.y);
    uint32_t h1 = pack_bf16x2(r.z, r.w);
    __nv_bfloat162 hb0 = *reinterpret_cast<__nv_bfloat162*>(&h0);
    __nv_bfloat162 hb1 = *reinterpret_cast<__nv_bfloat162*>(&h1);
    float2 hr0 = __bfloat1622float2(hb0);
    float2 hr1 = __bfloat1622float2(hb1);
    uint32_t l0 = pack_bf16x2(r.x - hr0.x, r.y - hr0.y);
    uint32_t l1 = pack_bf16x2(r.z - hr1.x, r.w - hr1.y);

    int T = node >> 7, rr = node & 127;
    int c8 = lane >> 4;
    int g8 = (lane >> 1) & 7;
    int half = lane & 1;
    size_t base = ((size_t)T * 2 + c8) * 16384
                + SW128((uint32_t)(rr * 128 + g8 * 16)) + half * 8;
    *(uint2*)(g_ahi + base) = make_uint2(h0, h1);
    *(uint2*)(g_alo + base) = make_uint2(l0, l1);
}

// ================== persistent fused layer kernel ==================
// PASS 1: raw y = A@W1 in TMEM; RAW stats -> g_ssum/g_ssq; next-tile A-ch0 prefetch.
// PASS 2: recompute y, BN+ReLU in-register, GEMM2 -> h2 + stats;
//          next-tile A-ch0 prefetch overlaps the final h2 epilogue.
#define P_PTR   0
#define P_MBAR  16
#define P_SC    32
#define P_SH    1056
#define P_SB    2080
#define P_SSL   3104
#define P_SQL   4128
#define P_PSUM  5152
#define P_PSQ   6176
#define P_A1HI  8192
#define P_A1LO  24576
#define P_B1HI  40960
#define P_B1LO  73728
#define P_SMEM  106496
#define TG_IDESC 0x8200490u

template<int PASS>
__global__ void __launch_bounds__(256, 2) pass_k(
    const uint8_t* __restrict__ Ahi, const uint8_t* __restrict__ Alo,
    const __nv_bfloat16* __restrict__ B1hi, const __nv_bfloat16* __restrict__ B1lo,
    const __nv_bfloat16* __restrict__ B2hi, const __nv_bfloat16* __restrict__ B2lo,
    const float* __restrict__ b1, const float* __restrict__ b2,
    const float* __restrict__ g1, const float* __restrict__ be1, float invM,
    float* __restrict__ C, int M, int ntiles)
{
    extern __shared__ char smem[];
    const uint32_t sb = smem_u32(smem);
    const int t = threadIdx.x, wid = t >> 5, lid = t & 31;
    float* sSc = reinterpret_cast<float*>(smem + P_SC);
    float* sSh = reinterpret_cast<float*>(smem + P_SH);
    float* sB  = reinterpret_cast<float*>(smem + P_SB);
    float* ssl = reinterpret_cast<float*>(smem + P_SSL);
    float* sql = reinterpret_cast<float*>(smem + P_SQL);
    float* psum = reinterpret_cast<float*>(smem + P_PSUM);
    float* psq  = reinterpret_cast<float*>(smem + P_PSQ);
    float* statbuf = reinterpret_cast<float*>(smem + P_B1HI);

    if (PASS == 1 && blockIdx.x == 0 && t < 128) {
        g_ssum2[t] = 0.f;
        g_ssq2[t]  = 0.f;
    }
    if (wid == 0) TC_ALLOC(sb + P_PTR, 256);
    if (t == 0) MB_INIT(sb + P_MBAR, 1);
    if (PASS == 2) {
        // raw stats: mean_raw = ssum*invM ; y = raw + b1 -> fold into shift
        float mraw = g_ssum[t] * invM;
        float var  = g_ssq[t] * invM - mraw * mraw;
        float sc   = g1[t] * rsqrtf(var + 1e-5f);
        sSc[t] = sc;
        sSh[t] = fmaf(-mraw, sc, be1[t]);
        if (t < 128) sB[t] = b2[t];
    }
    __syncthreads();
    uint32_t tmem;
    asm volatile("ld.shared.b32 %0, [%1];" : "=r"(tmem) : "r"(sb + P_PTR));

    const uint64_t dA1hi = make_desc(sb + P_A1HI);
    const uint64_t dA1lo = make_desc(sb + P_A1LO);
    const uint64_t dB1hi = make_desc(sb + P_B1HI);
    const uint64_t dB1lo = make_desc(sb + P_B1LO);

    int pc = 0;

#define CPASYNC_A1(TILE, CH)                                                    \
    {                                                                           \
        size_t abase = ((size_t)(TILE) * 2 + (CH)) * 16384;                     \
        _Pragma("unroll")                                                       \
        for (int it = 0; it < 4; it++) {                                        \
            uint32_t o = (uint32_t)(t + it * 256) * 16;                         \
            CP_ASYNC16(sb + P_A1HI + o, Ahi + abase + o);                       \
            CP_ASYNC16(sb + P_A1LO + o, Alo + abase + o);                       \
        }                                                                       \
    }
#define CPASYNC_B1(CH)                                                          \
    {                                                                           \
        int kb_ = (CH) * 64;                                                    \
        _Pragma("unroll")                                                       \
        for (int it = 0; it < 8; it++) {                                        \
            int idx = t + it * 256;                                             \
            int r_ = idx >> 3, kg_ = idx & 7;                                   \
            uint32_t so_ = SW128((uint32_t)(r_ * 128 + kg_ * 16));              \
            size_t bo_ = (size_t)r_ * 128 + kb_ + kg_ * 8;                      \
            CP_ASYNC16(sb + P_B1HI + so_, B1hi + bo_);                          \
            CP_ASYNC16(sb + P_B1LO + so_, B1lo + bo_);                          \
        }                                                                       \
        CP_COMMIT();                                                            \
    }
#define MMA1_CHUNK(CH)                                                          \
    if (wid == 0 && elect_one()) {                                              \
        _Pragma("unroll")                                                       \
        for (int T = 0; T < 2; T++) {                                           \
            uint64_t bh = dB1hi + T * 1024;                                     \
            uint64_t bl = dB1lo + T * 1024;                                     \
            uint32_t dt = tmem + T * 128;                                       \
            _Pragma("unroll")                                                   \
            for (int s = 0; s < 4; s++)                                         \
                mma_bf16_ss(dt, dA1hi + s * 2, bh + s * 2, TG_IDESC,            \
                            ((CH) == 0 && s == 0) ? 0u : 1u);                   \
            _Pragma("unroll")                                                   \
            for (int s = 0; s < 4; s++)                                         \
                mma_bf16_ss(dt, dA1hi + s * 2, bl + s * 2, TG_IDESC, 1u);       \
            _Pragma("unroll")                                                   \
            for (int s = 0; s < 4; s++)                                         \
                mma_bf16_ss(dt, dA1lo + s * 2, bh + s * 2, TG_IDESC, 1u);       \
        }                                                                       \
        TC_COMMIT(sb + P_MBAR);                                                 \
    }

    // prefetch first tile's A-ch0 before the loop (both passes)
    if (blockIdx.x < ntiles) {
        CPASYNC_A1(blockIdx.x, 0);
        CP_COMMIT();
    }

    for (int tile = blockIdx.x; tile < ntiles; tile += gridDim.x) {
        const int bm = tile * 128;

        // -------- phase 1: y = A @ W1 (2 k-chunks); A-ch0 already prefetched --------
        CPASYNC_B1(0);
        CP_WAIT0();
        FENCE_ASYNC();
        __syncthreads();
        MMA1_CHUNK(0);
        MB_WAIT(sb + P_MBAR, pc & 1); pc++;
        CPASYNC_A1(tile, 1);
        CPASYNC_B1(1);
        CP_WAIT0();
        FENCE_ASYNC();
        __syncthreads();
        MMA1_CHUNK(1);
        MB_WAIT(sb + P_MBAR, pc & 1); pc++;
        TC_FENCE_AFTER();

        if (PASS == 1) {
            // prefetch next tile's A-ch0 (A smem free; overlaps epilogue)
            int nxt = tile + gridDim.x;
            if (nxt < ntiles) {
                __syncthreads();   // all MMA-consumers past; safe to overwrite A
                CPASYNC_A1(nxt, 0);
                CP_COMMIT();
            }
            // -------- RAW y stats (no bias, no mask: pad rows are zero) --------
            for (int pr = 0; pr < 4; pr++) {
                if (wid < 4) {
                    int r = wid * 32 + lid;
                    uint32_t r0[32], r1[32];
                    LDTM32(r0, tmem + pr * 64);
                    LDTM32(r1, tmem + pr * 64 + 32);
                    TC_WAIT_LD();
#pragma unroll
                    for (int i = 0; i < 32; i++) {
                        statbuf[r * 66 + i]      = __uint_as_float(r0[i]);
                        statbuf[r * 66 + 32 + i] = __uint_as_float(r1[i]);
                    }
                }
                __syncthreads();
                {
                    int c = t & 63, h = t >> 6;
                    float s = 0.f, q = 0.f;
#pragma unroll 8
                    for (int rr = 0; rr < 32; rr++) {
                        float v = statbuf[(h * 32 + rr) * 66 + c];
                        s += v;
                        q = fmaf(v, v, q);
                    }
                    psum[h * 64 + c] = s;
                    psq[h * 64 + c]  = q;
                }
                __syncthreads();
                if (t < 64) {
                    ssl[pr * 64 + t] = psum[t] + psum[64 + t] + psum[128 + t] + psum[192 + t];
                    sql[pr * 64 + t] = psq[t]  + psq[64 + t]  + psq[128 + t]  + psq[192 + t];
                }
                __syncthreads();
            }
            if (wid < 4) TC_FENCE_BEFORE();
            __syncthreads();
            atomicAdd(&g_ssum[t], ssl[t]);
            atomicAdd(&g_ssq[t],  sql[t]);
            __syncthreads();
        } else {
            // -------- phase 2: h2 = bnrelu(y) @ W2 + b2 --------
            const uint64_t dB2hi = make_desc(sb + P_A1HI);
            const uint64_t dB2lo = make_desc(sb + P_A1LO);

#define CPASYNC_B2_HALF(CH)                                                     \
    {                                                                           \
        int kb_ = (CH) * 64;                                                    \
        _Pragma("unroll")                                                       \
        for (int it = 0; it < 8; it++) {                                        \
            int idx = (t - 128) + it * 128;                                     \
            int r_ = idx >> 3, kg_ = idx & 7;                                   \
            uint32_t so_ = SW128((uint32_t)(r_ * 128 + kg_ * 16));              \
            size_t bo_ = (size_t)r_ * 256 + kb_ + kg_ * 8;                      \
            CP_ASYNC16(sb + P_A1HI + so_, B2hi + bo_);                          \
            CP_ASYNC16(sb + P_A1LO + so_, B2lo + bo_);                          \
        }                                                                       \
        CP_COMMIT();                                                            \
        CP_WAIT0();                                                             \
    }
#define CPASYNC_B2_ALL(CH)                                                      \
    {                                                                           \
        int kb_ = (CH) * 64;                                                    \
        _Pragma("unroll")                                                       \
        for (int it = 0; it < 4; it++) {                                        \
            int idx = t + it * 256;                                             \
            int r_ = idx >> 3, kg_ = idx & 7;                                   \
            uint32_t so_ = SW128((uint32_t)(r_ * 128 + kg_ * 16));              \
            size_t bo_ = (size_t)r_ * 256 + kb_ + kg_ * 8;                      \
            CP_ASYNC16(sb + P_A1HI + so_, B2hi + bo_);                          \
            CP_ASYNC16(sb + P_A1LO + so_, B2lo + bo_);                          \
        }                                                                       \
        CP_COMMIT();                                                            \
        CP_WAIT0();                                                             \
    }
#define MMA2(SLOT, EN0)                                                         \
    if (wid == 0 && elect_one()) {                                              \
        uint64_t ah = make_desc(sb + P_B1HI + (SLOT) * 16384);                  \
        uint64_t al = make_desc(sb + P_B1LO + (SLOT) * 16384);                  \
        _Pragma("unroll")                                                       \
        for (int s = 0; s < 4; s++)                                             \
            mma_bf16_ss(tmem, ah + s * 2, dB2hi + s * 2, TG_IDESC,              \
                        ((EN0) && s == 0) ? 0u : 1u);                           \
        _Pragma("unroll")                                                       \
        for (int s = 0; s < 4; s++)                                             \
            mma_bf16_ss(tmem, ah + s * 2, dB2lo + s * 2, TG_IDESC, 1u);         \
        _Pragma("unroll")                                                       \
        for (int s = 0; s < 4; s++)                                             \
            mma_bf16_ss(tmem, al + s * 2, dB2hi + s * 2, TG_IDESC, 1u);         \
        TC_COMMIT(sb + P_MBAR);                                                 \
    }

#pragma unroll
            for (int half = 0; half < 2; half++) {
                if (wid < 4) {
                    int r = wid * 32 + lid;
#pragma unroll
                    for (int p2 = 0; p2 < 2; p2++) {
                        int b0 = half * 4 + p2 * 2;
                        uint32_t r0[32], r1[32];
                        LDTM32(r0, tmem + b0 * 32);
                        LDTM32(r1, tmem + (b0 + 1) * 32);
                        TC_WAIT_LD();
                        float v[64];
#pragma unroll
                        for (int i = 0; i < 32; i++) {
                            int c0 = b0 * 32 + i, c1 = (b0 + 1) * 32 + i;
                            v[i]      = fmaxf(fmaf(__uint_as_float(r0[i]), sSc[c0], sSh[c0]), 0.f);
                            v[32 + i] = fmaxf(fmaf(__uint_as_float(r1[i]), sSc[c1], sSh[c1]), 0.f);
                        }
#pragma unroll
                        for (int bb = 0; bb < 2; bb++) {
                            int blk = b0 + bb;
                            int slot = (blk >> 1) & 1;
                            const float* vv = v + bb * 32;
#pragma unroll
                            for (int q = 0; q < 4; q++) {
                                uint32_t h[4], lo[4];
#pragma unroll
                                for (int p = 0; p < 4; p++) {
                                    float a0 = vv[q * 8 + p * 2], a1 = vv[q * 8 + p * 2 + 1];
                                    h[p] = pack_bf16x2(a0, a1);
                                    __nv_bfloat162 hb = *reinterpret_cast<__nv_bfloat162*>(&h[p]);
                                    float2 hr = __bfloat1622float2(hb);
                                    lo[p] = pack_bf16x2(a0 - hr.x, a1 - hr.y);
                                }
                                uint32_t so = SW128((uint32_t)(r * 128 + (blk & 1) * 64 + q * 16));
                                *(uint4*)(smem + P_B1HI + slot * 16384 + so) = make_uint4(h[0], h[1], h[2], h[3]);
                                *(uint4*)(smem + P_B1LO + slot * 16384 + so) = make_uint4(lo[0], lo[1], lo[2], lo[3]);
                            }
                        }
                    }
                    TC_FENCE_BEFORE();
                } else {
                    CPASYNC_B2_HALF(2 * half);
                }
                FENCE_ASYNC();
                __syncthreads();
                MMA2(0, half == 0);
                MB_WAIT(sb + P_MBAR, pc & 1); pc++;
                CPASYNC_B2_ALL(2 * half + 1);
                FENCE_ASYNC();
                __syncthreads();
                MMA2(1, false);
                MB_WAIT(sb + P_MBAR, pc & 1); pc++;
                TC_FENCE_AFTER();
            }

#undef CPASYNC_B2_HALF
#undef CPASYNC_B2_ALL
#undef MMA2

            // prefetch next tile's A-ch0 into the (now free) B2 buffer region,
            // overlapping the final h2 epilogue below.
            {
                int nxt = tile + gridDim.x;
                if (nxt < ntiles) {
                    __syncthreads();   // all B2 staging + MMA consumption done
                    CPASYNC_A1(nxt, 0);
                    CP_COMMIT();
                }
            }

            // -------- final epilogue: h2 --------
            for (int pr = 0; pr < 2; pr++) {
                if (wid < 4) {
                    int r = wid * 32 + lid;
                    int grow = bm + r;
                    uint32_t r0[32], r1[32];
                    LDTM32(r0, tmem + pr * 64);
                    LDTM32(r1, tmem + pr * 64 + 32);
                    TC_WAIT_LD();
                    float v0[32], v1[32];
#pragma unroll
                    for (int i = 0; i < 32; i++) {
                        v0[i] = __uint_as_float(r0[i]) + sB[pr * 64 + i];
                        v1[i] = __uint_as_float(r1[i]) + sB[pr * 64 + 32 + i];
                    }
                    if (grow < M) {
                        float* cp = C + (size_t)grow * 128 + pr * 64;
#pragma unroll
                        for (int q = 0; q < 8; q++) {
                            *(float4*)(cp + q * 4)      = *(float4*)(v0 + q * 4);
                            *(float4*)(cp + 32 + q * 4) = *(float4*)(v1 + q * 4);
                        }
                    } else {
#pragma unroll
                        for (int i = 0; i < 32; i++) { v0[i] = 0.f; v1[i] = 0.f; }
                    }
#pragma unroll
                    for (int i = 0; i < 32; i++) {
                        statbuf[r * 66 + i]      = v0[i];
                        statbuf[r * 66 + 32 + i] = v1[i];
                    }
                }
                __syncthreads();
                {
                    int c = t & 63, h = t >> 6;
                    float s = 0.f, q = 0.f;
#pragma unroll 8
                    for (int rr = 0; rr < 32; rr++) {
                        float vv = statbuf[(h * 32 + rr) * 66 + c];
                        s += vv;
                        q = fmaf(vv, vv, q);
                    }
                    psum[h * 64 + c] = s;
                    psq[h * 64 + c]  = q;
                }
                __syncthreads();
                if (t < 64) {
                    ssl[pr * 64 + t] = psum[t] + psum[64 + t] + psum[128 + t] + psum[192 + t];
                    sql[pr * 64 + t] = psq[t]  + psq[64 + t]  + psq[128 + t]  + psq[192 + t];
                }
                __syncthreads();
            }
            if (wid < 4) TC_FENCE_BEFORE();
            __syncthreads();
            if (t < 128) {
                atomicAdd(&g_ssum2[t], ssl[t]);
                atomicAdd(&g_ssq2[t],  sql[t]);
            }
            __syncthreads();
        }
    }

#undef CPASYNC_A1
#undef CPASYNC_B1
#undef MMA1_CHUNK

    CP_WAIT0();   // drain any dangling prefetch
    if (t == 0) MB_INVAL(sb + P_MBAR);
    if (wid == 0) TC_DEALLOC(tmem, 256);
}

// ---------------- readout pooling (computes outer BN inline) ----------------
__global__ void pool_k(const void* __restrict__ batch, int n,
                       const float* __restrict__ gamma, const float* __restrict__ beta,
                       float invM) {
    long long t = (long long)blockIdx.x * blockDim.x + threadIdx.x;
    long long i = t >> 5;
    if (i >= n) return;
    int lane = (int)(t & 31);
    long long g;
    if (g_i64flag) g = ((const long long*)batch)[i];
    else           g = (long long)((const int*)batch)[i];
    int c = lane * 4;
    float sc[4], sh[4];
#pragma unroll
    for (int j = 0; j < 4; j++) {
        float m   = g_ssum2[c + j] * invM;
        float var = g_ssq2[c + j] * invM - m * m;
        sc[j] = gamma[c + j] * rsqrtf(var + 1e-5f);
        sh[j] = beta[c + j] - m * sc[j];
    }
    float4 v = ((const float4*)g_h2)[i * 32 + lane];
    float r0 = fmaxf(fmaf(v.x, sc[0], sh[0]), 0.f);
    float r1 = fmaxf(fmaf(v.y, sc[1], sh[1]), 0.f);
    float r2 = fmaxf(fmaf(v.z, sc[2], sh[2]), 0.f);
    float r3 = fmaxf(fmaf(v.w, sc[3], sh[3]), 0.f);
    float* ps = g_ps + g * 128 + c;
    asm volatile("red.global.add.v4.f32 [%0], {%1, %2, %3, %4};"
                 :: "l"(ps), "f"(r0), "f"(r1), "f"(r2), "f"(r3) : "memory");
    unsigned int* mx = (unsigned int*)(g_pmx + g * 128 + c);
    atomicMax(mx + 0, __float_as_uint(r0));
    atomicMax(mx + 1, __float_as_uint(r1));
    atomicMax(mx + 2, __float_as_uint(r2));
    atomicMax(mx + 3, __float_as_uint(r3));
    if (lane == 0) atomicAdd(&g_cnt[g], 1.0f);
}

// ---------------- classifier ----------------
__global__ void cgemm1_k(const float* __restrict__ cW1, const float* __restrict__ cb1) {
    int g = blockIdx.x;
    int j = threadIdx.x;
    __shared__ float z[384];
    float cnt = fmaxf(g_cnt[g], 1.0f);
    float sv = g_ps[g * 128 + j];
    z[j]       = sv;
    z[128 + j] = sv / cnt;
    z[256 + j] = g_pmx[g * 128 + j];
    __syncthreads();
    float acc = cb1[j];
#pragma unroll 8
    for (int k = 0; k < 384; k++)
        acc = fmaf(z[k], cW1[k * 128 + j], acc);
    g_z1[g * 128 + j] = acc;
}

__global__ void cstats_k(const float* __restrict__ cg, const float* __restrict__ cbeta) {
    int j = threadIdx.x;
    float s = 0.f, q = 0.f;
    for (int g = 0; g < GCNT; g++) {
        float v = g_z1[g * 128 + j];
        s += v; q += v * v;
    }
    float m   = s * (1.0f / GCNT);
    float var = q * (1.0f / GCNT) - m * m;
    float sc  = cg[j] * rsqrtf(var + 1e-5f);
    g_scale[j] = sc;
    g_shift[j] = cbeta[j] - m * sc;
}

__global__ void chead_k(const float* __restrict__ cW2, const float* __restrict__ cb2,
                        const float* __restrict__ cW3, const float* __restrict__ cb3,
                        float* __restrict__ out) {
    int g = blockIdx.x;
    int j = threadIdx.x;
    __shared__ float a[128];
    __shared__ float z2[64];
    for (int k = j; k < 128; k += 64)
        a[k] = fmaxf(fmaf(g_z1[g * 128 + k], g_scale[k], g_shift[k]), 0.f);
    __syncthreads();
    float acc = cb2[j];
#pragma unroll 8
    for (int k = 0; k < 128; k++)
        acc = fmaf(a[k], cW2[k * 64 + j], acc);
    z2[j] = fmaxf(acc, 0.f);
    __syncthreads();
    if (j < 2) {
        float o = cb3[j];
#pragma unroll 8
        for (int k = 0; k < 64; k++)
            o = fmaf(z2[k], cW3[k * 2 + j], o);
        out[g * 2 + j] = o;
    }
}

// ---------------- launcher ----------------
extern "C" void kernel_launch(void* const* d_in, const int* in_sizes, int n_in,
                              void* d_out, int out_size) {
    const float* x     = (const float*)d_in[0];
    const void*  ei    = d_in[1];
    const void*  batch = d_in[2];
    int base = (in_sizes[3] == 1) ? 4 : 3;
    const float* W1    = (const float*)d_in[base + 0];
    const float* b1    = (const float*)d_in[base + 1];
    const float* g1    = (const float*)d_in[base + 2];
    const float* be1   = (const float*)d_in[base + 3];
    const float* W2    = (const float*)d_in[base + 4];
    const float* b2    = (const float*)d_in[base + 5];
    const float* gbn   = (const float*)d_in[base + 6];
    const float* bbn   = (const float*)d_in[base + 7];
    const float* eps   = (const float*)d_in[base + 8];
    const float* cW1   = (const float*)d_in[base + 9];
    const float* cb1   = (const float*)d_in[base + 10];
    const float* cg    = (const float*)d_in[base + 11];
    const float* cbeta = (const float*)d_in[base + 12];
    const float* cW2   = (const float*)d_in[base + 13];
    const float* cb2   = (const float*)d_in[base + 14];
    const float* cW3   = (const float*)d_in[base + 15];
    const float* cb3   = (const float*)d_in[base + 16];

    int n = in_sizes[0] / 128;
    long long E = (long long)in_sizes[1] / 2;
    int n32 = n * 32;
    int nb = (n32 + 255) / 256;
    int gx = (n + 127) / 128;
    int pgrid = (gx < 296) ? gx : 296;
    int eblk = (int)((E + 255) / 256);
    int nscan = (n + 1023) / 1024;
    int ablk = (n * 32 + 255) / 256;
    float invM = 1.0f / (float)n;

    static int smem_set = 0;
    if (!smem_set) {
        cudaFuncSetAttribute(pass_k<1>, cudaFuncAttributeMaxDynamicSharedMemorySize, P_SMEM);
        cudaFuncSetAttribute(pass_k<2>, cudaFuncAttributeMaxDynamicSharedMemorySize, P_SMEM);
        smem_set = 1;
    }

    float *p_h2;
    uint8_t *p_ahi, *p_alo;
    __nv_bfloat16 *p_b1hi, *p_b1lo, *p_b2hi, *p_b2lo;
    cudaGetSymbolAddress((void**)&p_h2,  g_h2);
    cudaGetSymbolAddress((void**)&p_ahi, g_ahi);
    cudaGetSymbolAddress((void**)&p_alo, g_alo);
    cudaGetSymbolAddress((void**)&p_b1hi, g_b1hi);
    cudaGetSymbolAddress((void**)&p_b1lo, g_b1lo);
    cudaGetSymbolAddress((void**)&p_b2hi, g_b2hi);
    cudaGetSymbolAddress((void**)&p_b2lo, g_b2lo);

    detect_k<<<1, 1>>>((const unsigned int*)ei);
    wconv_k<<<(NLAYER * 256 * 128 + 255) / 256, 256>>>(W1, W2);
    zero_k<<<512, 256>>>(n, gx);

    // CSR build (once; edges shared by all layers)
    count_k<<<eblk, 256>>>(ei, E);
    scanA_k<<<nscan, 256>>>(n);
    scanB_k<<<1, 32>>>(nscan);
    scanC_k<<<nscan, 256>>>(n);
    fill_k<<<eblk, 256>>>(ei, E);

    for (int l = 0; l < 4; l++) {
        if (l == 0)
            agg_k<false><<<ablk, 256>>>(x, eps, l, n, nullptr, nullptr, invM);
        else
            agg_k<true><<<ablk, 256>>>(p_h2, eps, l, n,
                                       gbn + (l - 1) * 128, bbn + (l - 1) * 128, invM);

        pass_k<1><<<pgrid, 256, P_SMEM>>>(
            p_ahi, p_alo,
            p_b1hi + (size_t)l * 32768, p_b1lo + (size_t)l * 32768,
            p_b2hi + (size_t)l * 32768, p_b2lo + (size_t)l * 32768,
            b1 + l * 256, b2 + l * 128, g1 + l * 256, be1 + l * 256, invM,
            nullptr, n, gx);
        pass_k<2><<<pgrid, 256, P_SMEM>>>(
            p_ahi, p_alo,
            p_b1hi + (size_t)l * 32768, p_b1lo + (size_t)l * 32768,
            p_b2hi + (size_t)l * 32768, p_b2lo + (size_t)l * 32768,
            b1 + l * 256, b2 + l * 128, g1 + l * 256, be1 + l * 256, invM,
            p_h2, n, gx);
    }

    pool_k<<<nb, 256>>>(batch, n, gbn + 3 * 128, bbn + 3 * 128, invM);
    cgemm1_k<<<GCNT, 128>>>(cW1, cb1);
    cstats_k<<<1, 128>>>(cg, cbeta);
    chead_k<<<GCNT, 64>>>(cW2, cb2, cW3, cb3, (float*)d_out);
}

// round 15
// speedup vs baseline: 1.0246x; 1.0246x over previous
#include <cuda_runtime.h>
#include <cuda_bf16.h>
#include <cstdint>
#include <cstddef>

// Problem constants (fixed shapes)
#define NMAX 100000
#define EMAX 500000
#define GCNT 512
#define NLAYER 4
#define NTILE ((NMAX + 127) / 128)   // 782

// tcgen05 only exists in the arch-specific (sm_103a) device pass.
#if defined(__CUDA_ARCH__) && defined(__CUDA_ARCH_FEAT_SM103_ALL)
#define HAS_TC 1
#else
#define HAS_TC 0
#endif

// ---------------- device scratch ----------------
__device__ float g_h2 [NMAX * 128];
// aggregated layer input, pre-split bf16 hi/lo, pre-swizzled smem image:
// [tile][chunk(2)][16KB image]  where image[SW128(row*128 + kg*16)]
__device__ uint8_t g_ahi[(size_t)NTILE * 32768];
__device__ uint8_t g_alo[(size_t)NTILE * 32768];
__device__ float g_ssum [256];
__device__ float g_ssq  [256];
__device__ float g_ssum2[128];
__device__ float g_ssq2 [128];
__device__ float g_scale[256];   // used by classifier only now
__device__ float g_shift[256];
__device__ float g_ps [GCNT * 128];
__device__ float g_pmx[GCNT * 128];
__device__ float g_cnt[GCNT];
__device__ float g_z1 [GCNT * 128];
__device__ int   g_i64flag;

// CSR (built once per launch; edges fixed across layers)
__device__ int g_deg [NMAX];
__device__ int g_off [NMAX];
__device__ int g_cur [NMAX];
__device__ int g_csr [EMAX];
__device__ int g_bsum[128];
__device__ int g_bscn[128];

// pre-split weights, B layout: [layer][n(out)][k(in)] bf16, K-major rows
__device__ __nv_bfloat16 g_b1hi[NLAYER * 256 * 128];
__device__ __nv_bfloat16 g_b1lo[NLAYER * 256 * 128];
__device__ __nv_bfloat16 g_b2hi[NLAYER * 128 * 256];
__device__ __nv_bfloat16 g_b2lo[NLAYER * 128 * 256];

// ---------------- PTX helpers ----------------
__device__ __forceinline__ uint32_t smem_u32(const void* p) {
    uint32_t a;
    asm("{ .reg .u64 t; cvta.to.shared.u64 t, %1; cvt.u32.u64 %0, t; }" : "=r"(a) : "l"(p));
    return a;
}
__device__ __forceinline__ uint32_t elect_one() {
    uint32_t p;
    asm volatile("{ .reg .pred p; elect.sync _|p, 0xFFFFFFFF; selp.b32 %0, 1, 0, p; }" : "=r"(p));
    return p;
}
#define SW128(o) ((o) ^ (((o) >> 3) & 0x70))
static __device__ __forceinline__ uint64_t make_desc(uint32_t addr) {
    return ((uint64_t)2 << 61) | ((uint64_t)1 << 46) | ((uint64_t)64 << 32) |
           ((uint64_t)1 << 16) | ((uint64_t)(addr >> 4) & 0x3FFF);
}

#if HAS_TC
__device__ __forceinline__ void mma_bf16_ss(uint32_t d, uint64_t a, uint64_t b,
                                            uint32_t idesc, uint32_t en) {
    asm volatile(
        "{\n\t.reg .pred p;\n\tsetp.ne.u32 p, %4, 0;\n\t"
        "tcgen05.mma.cta_group::1.kind::f16 [%0], %1, %2, %3, {%5, %5, %5, %5}, p;\n\t}"
        :: "r"(d), "l"(a), "l"(b), "r"(idesc), "r"(en), "r"(0u) : "memory");
}
#define TC_ALLOC(sm, n)  asm volatile("tcgen05.alloc.cta_group::1.sync.aligned.shared::cta.b32 [%0], %1;" :: "r"(sm), "r"((uint32_t)(n)) : "memory")
#define TC_DEALLOC(t, n) asm volatile("tcgen05.dealloc.cta_group::1.sync.aligned.b32 %0, %1;" :: "r"(t), "r"((uint32_t)(n)))
#define TC_COMMIT(mb)    asm volatile("tcgen05.commit.cta_group::1.mbarrier::arrive::one.shared::cluster.b64 [%0];" :: "r"(mb) : "memory")
#define TC_FENCE_AFTER() asm volatile("tcgen05.fence::after_thread_sync;" ::: "memory")
#define TC_FENCE_BEFORE() asm volatile("tcgen05.fence::before_thread_sync;" ::: "memory")
#define TC_WAIT_LD()     asm volatile("tcgen05.wait::ld.sync.aligned;" ::: "memory")
#define LDTM32(r, a)                                                            \
    asm volatile("tcgen05.ld.sync.aligned.32x32b.x32.b32 "                      \
        "{%0,%1,%2,%3,%4,%5,%6,%7,%8,%9,%10,%11,%12,%13,%14,%15,"               \
        "%16,%17,%18,%19,%20,%21,%22,%23,%24,%25,%26,%27,%28,%29,%30,%31}, [%32];" \
        : "=r"((r)[0]),"=r"((r)[1]),"=r"((r)[2]),"=r"((r)[3]),                  \
          "=r"((r)[4]),"=r"((r)[5]),"=r"((r)[6]),"=r"((r)[7]),                  \
          "=r"((r)[8]),"=r"((r)[9]),"=r"((r)[10]),"=r"((r)[11]),                \
          "=r"((r)[12]),"=r"((r)[13]),"=r"((r)[14]),"=r"((r)[15]),              \
          "=r"((r)[16]),"=r"((r)[17]),"=r"((r)[18]),"=r"((r)[19]),              \
          "=r"((r)[20]),"=r"((r)[21]),"=r"((r)[22]),"=r"((r)[23]),              \
          "=r"((r)[24]),"=r"((r)[25]),"=r"((r)[26]),"=r"((r)[27]),              \
          "=r"((r)[28]),"=r"((r)[29]),"=r"((r)[30]),"=r"((r)[31])               \
        : "r"(a))
#define MB_WAIT(mb, par) do {                                                   \
    uint32_t _m = (mb), _p = (par), _d;                                         \
    asm volatile("{ .reg .pred p; mbarrier.try_wait.parity.acquire.cta.shared::cta.b64 p, [%1], %2; selp.b32 %0, 1, 0, p; }" \
                 : "=r"(_d) : "r"(_m), "r"(_p) : "memory");                     \
    if (!_d) {                                                                  \
        asm volatile("{ .reg .pred P1; W%=: mbarrier.try_wait.parity.acquire.cta.shared::cta.b64 P1, [%0], %1, 0x989680; @P1 bra.uni D%=; bra.uni W%=; D%=: }" \
                     :: "r"(_m), "r"(_p) : "memory");                           \
    }                                                                           \
} while (0)
#else
__device__ __forceinline__ void mma_bf16_ss(uint32_t, uint64_t, uint64_t, uint32_t, uint32_t) {}
#define TC_ALLOC(sm, n)   ((void)0)
#define TC_DEALLOC(t, n)  ((void)0)
#define TC_COMMIT(mb)     ((void)0)
#define TC_FENCE_AFTER()  ((void)0)
#define TC_FENCE_BEFORE() ((void)0)
#define TC_WAIT_LD()      ((void)0)
#define LDTM32(r, a)      do { _Pragma("unroll") for (int _i = 0; _i < 32; _i++) (r)[_i] = 0u; } while (0)
#define MB_WAIT(mb, par)  ((void)0)
#endif

#define MB_INIT(mb, c)   asm volatile("mbarrier.init.shared.b64 [%0], %1;" :: "r"(mb), "r"((uint32_t)(c)) : "memory")
#define MB_INVAL(mb)     asm volatile("mbarrier.inval.shared.b64 [%0];" :: "r"(mb) : "memory")
#define FENCE_ASYNC()    asm volatile("fence.proxy.async.shared::cta;" ::: "memory")
#define CP_ASYNC16(dst, src) asm volatile("cp.async.ca.shared.global [%0], [%1], 16;" :: "r"(dst), "l"(src) : "memory")
#define CP_COMMIT()      asm volatile("cp.async.commit_group;" ::: "memory")
#define CP_WAIT0()       asm volatile("cp.async.wait_group 0;" ::: "memory")

// ---------------- dtype detection ----------------
__global__ void detect_k(const unsigned int* __restrict__ e) {
    unsigned acc = 0;
    for (int i = 1; i < 128; i += 2) acc |= e[i];
    g_i64flag = (acc == 0u) ? 1 : 0;
}

// ---------------- weight split fp32 -> bf16 hi/lo ----------------
__global__ void wconv_k(const float* __restrict__ W1, const float* __restrict__ W2) {
    int i = blockIdx.x * 256 + threadIdx.x;
    const int tot = NLAYER * 256 * 128;
    if (i >= tot) return;
    int l = i / (256 * 128), rem = i % (256 * 128);
    {
        int n = rem / 128, k = rem % 128;
        float w = W1[l * 32768 + k * 256 + n];
        __nv_bfloat16 h = __float2bfloat16(w);
        g_b1hi[i] = h;
        g_b1lo[i] = __float2bfloat16(w - __bfloat162float(h));
    }
    {
        int n = rem / 256, k = rem % 256;
        float w = W2[l * 32768 + k * 128 + n];
        __nv_bfloat16 h = __float2bfloat16(w);
        g_b2hi[i] = h;
        g_b2lo[i] = __float2bfloat16(w - __bfloat162float(h));
    }
}

// ---------------- zero (grid-stride; covers n + pad tile image) ----------------
__global__ void zero_k(int n, int gx) {
    int tot = (n > GCNT * 128) ? n : GCNT * 128;
    for (int i = blockIdx.x * blockDim.x + threadIdx.x; i < tot;
         i += gridDim.x * blockDim.x) {
        if (i < 256) { g_ssum[i] = 0.f; g_ssq[i] = 0.f; }
        if (i < 128) { g_ssum2[i] = 0.f; g_ssq2[i] = 0.f; }
        if (i < GCNT * 128) { g_ps[i] = 0.f; g_pmx[i] = 0.f; }
        if (i < GCNT) g_cnt[i] = 0.f;
        if (i < n) g_deg[i] = 0;
    }
    size_t lt = (size_t)(gx - 1) * 32768;
    for (int i = blockIdx.x * blockDim.x + threadIdx.x; i < 32768 / 16;
         i += gridDim.x * blockDim.x) {
        ((uint4*)(g_ahi + lt))[i] = make_uint4(0, 0, 0, 0);
        ((uint4*)(g_alo + lt))[i] = make_uint4(0, 0, 0, 0);
    }
}

// ---------------- CSR build ----------------
__global__ void count_k(const void* __restrict__ ei, long long E) {
    long long e = (long long)blockIdx.x * blockDim.x + threadIdx.x;
    if (e >= E) return;
    int d;
    if (g_i64flag) d = (int)((const long long*)ei)[E + e];
    else           d = ((const int*)ei)[E + e];
    atomicAdd(&g_deg[d], 1);
}

__global__ void scanA_k(int n) {
    __shared__ int sred[256];
    int blk = blockIdx.x, t = threadIdx.x;
    int base = blk * 1024 + t * 4;
    int s = 0;
#pragma unroll
    for (int j = 0; j < 4; j++) {
        int idx = base + j;
        if (idx < n) s += g_deg[idx];
    }
    sred[t] = s;
    __syncthreads();
    for (int o = 128; o > 0; o >>= 1) {
        if (t < o) sred[t] += sred[t + o];
        __syncthreads();
    }
    if (t == 0) g_bsum[blk] = sred[0];
}

__global__ void scanB_k(int nblk) {
    if (threadIdx.x == 0) {
        int run = 0;
        for (int i = 0; i < nblk; i++) { g_bscn[i] = run; run += g_bsum[i]; }
    }
}

__global__ void scanC_k(int n) {
    __shared__ int sth[256];
    int blk = blockIdx.x, t = threadIdx.x;
    int base = blk * 1024 + t * 4;
    int v[4];
    int s = 0;
#pragma unroll
    for (int j = 0; j < 4; j++) {
        int idx = base + j;
        v[j] = (idx < n) ? g_deg[idx] : 0;
        s += v[j];
    }
    sth[t] = s;
    __syncthreads();
    for (int o = 1; o < 256; o <<= 1) {
        int add = (t >= o) ? sth[t - o] : 0;
        __syncthreads();
        sth[t] += add;
        __syncthreads();
    }
    int tpre = (t > 0 ? sth[t - 1] : 0) + g_bscn[blk];
#pragma unroll
    for (int j = 0; j < 4; j++) {
        int idx = base + j;
        if (idx < n) { g_off[idx] = tpre; g_cur[idx] = tpre; }
        tpre += v[j];
    }
}

__global__ void fill_k(const void* __restrict__ ei, long long E) {
    long long e = (long long)blockIdx.x * blockDim.x + threadIdx.x;
    if (e >= E) return;
    int s, d;
    if (g_i64flag) {
        const long long* p = (const long long*)ei;
        s = (int)p[e]; d = (int)p[E + e];
    } else {
        const int* p = (const int*)ei;
        s = p[e]; d = p[E + e];
    }
    int pos = atomicAdd(&g_cur[d], 1);
    if (pos < EMAX) g_csr[pos] = s;
}

__device__ __forceinline__ uint32_t pack_bf16x2(float a, float b) {
    __nv_bfloat162 h = __float22bfloat162_rn(make_float2(a, b));
    return *reinterpret_cast<uint32_t*>(&h);
}

// ---------------- CSR aggregation + bf16 split + swizzled store ----------------
template<bool BN>
__global__ void __launch_bounds__(256) agg_k(
    const float* __restrict__ SRC, const float* __restrict__ epsp, int l, int n,
    const float* __restrict__ gamma, const float* __restrict__ beta, float invM) {
    if (BN && blockIdx.x == 0) {
        g_ssum[threadIdx.x] = 0.f;
        g_ssq[threadIdx.x]  = 0.f;
    }
    int node = (int)(((long long)blockIdx.x * blockDim.x + threadIdx.x) >> 5);
    int lane = threadIdx.x & 31;
    if (node >= n) return;
    float e = 1.0f + epsp[l];

    float sc0, sc1, sc2, sc3, sh0, sh1, sh2, sh3;
    if (BN) {
        int c = lane * 4;
#pragma unroll
        for (int j = 0; j < 4; j++) {
            float m   = g_ssum2[c + j] * invM;
            float var = g_ssq2[c + j] * invM - m * m;
            float sc  = gamma[c + j] * rsqrtf(var + 1e-5f);
            float sh  = beta[c + j] - m * sc;
            if (j == 0) { sc0 = sc; sh0 = sh; }
            else if (j == 1) { sc1 = sc; sh1 = sh; }
            else if (j == 2) { sc2 = sc; sh2 = sh; }
            else { sc3 = sc; sh3 = sh; }
        }
    }
#define FBN(v)                                                                   \
    if (BN) {                                                                    \
        v.x = fmaxf(fmaf(v.x, sc0, sh0), 0.f);                                   \
        v.y = fmaxf(fmaf(v.y, sc1, sh1), 0.f);                                   \
        v.z = fmaxf(fmaf(v.z, sc2, sh2), 0.f);                                   \
        v.w = fmaxf(fmaf(v.w, sc3, sh3), 0.f);                                   \
    }

    int beg = g_off[node];
    int deg = g_deg[node];

    float4 self = ((const float4*)SRC)[(size_t)node * 32 + lane];
    FBN(self);
    float4 a0 = make_float4(self.x * e, self.y * e, self.z * e, self.w * e);
    float4 a1 = make_float4(0.f, 0.f, 0.f, 0.f);
    float4 a2 = make_float4(0.f, 0.f, 0.f, 0.f);
    float4 a3 = make_float4(0.f, 0.f, 0.f, 0.f);

    int i = 0;
    for (; i + 4 <= deg; i += 4) {
        int s0 = g_csr[beg + i];
        int s1 = g_csr[beg + i + 1];
        int s2 = g_csr[beg + i + 2];
        int s3 = g_csr[beg + i + 3];
        float4 v0 = ((const float4*)SRC)[(size_t)s0 * 32 + lane];
        float4 v1 = ((const float4*)SRC)[(size_t)s1 * 32 + lane];
        float4 v2 = ((const float4*)SRC)[(size_t)s2 * 32 + lane];
        float4 v3 = ((const float4*)SRC)[(size_t)s3 * 32 + lane];
        FBN(v0); FBN(v1); FBN(v2); FBN(v3);
        a0.x += v0.x; a0.y += v0.y; a0.z += v0.z; a0.w += v0.w;
        a1.x += v1.x; a1.y += v1.y; a1.z += v1.z; a1.w += v1.w;
        a2.x += v2.x; a2.y += v2.y; a2.z += v2.z; a2.w += v2.w;
        a3.x += v3.x; a3.y += v3.y; a3.z += v3.z; a3.w += v3.w;
    }
    if (i < deg) {
        int rem = deg - i;
        int s0 = g_csr[beg + i];
        int s1 = g_csr[beg + ((rem > 1) ? i + 1 : i)];
        int s2 = g_csr[beg + ((rem > 2) ? i + 2 : i)];
        float4 v0 = ((const float4*)SRC)[(size_t)s0 * 32 + lane];
        float4 v1 = ((const float4*)SRC)[(size_t)s1 * 32 + lane];
        float4 v2 = ((const float4*)SRC)[(size_t)s2 * 32 + lane];
        FBN(v0); FBN(v1); FBN(v2);
        a1.x += v0.x; a1.y += v0.y; a1.z += v0.z; a1.w += v0.w;
        if (rem > 1) { a2.x += v1.x; a2.y += v1.y; a2.z += v1.z; a2.w += v1.w; }
        if (rem > 2) { a3.x += v2.x; a3.y += v2.y; a3.z += v2.z; a3.w += v2.w; }
    }
#undef FBN
    float4 r;
    r.x = (a0.x + a1.x) + (a2.x + a3.x);
    r.y = (a0.y + a1.y) + (a2.y + a3.y);
    r.z = (a0.z + a1.z) + (a2.z + a3.z);
    r.w = (a0.w + a1.w) + (a2.w + a3.w);

    uint32_t h0 = pack_bf16x2(r.x, r.y);
    uint32_t h1 = pack_bf16x2(r.z, r.w);
    __nv_bfloat162 hb0 = *reinterpret_cast<__nv_bfloat162*>(&h0);
    __nv_bfloat162 hb1 = *reinterpret_cast<__nv_bfloat162*>(&h1);
    float2 hr0 = __bfloat1622float2(hb0);
    float2 hr1 = __bfloat1622float2(hb1);
    uint32_t l0 = pack_bf16x2(r.x - hr0.x, r.y - hr0.y);
    uint32_t l1 = pack_bf16x2(r.z - hr1.x, r.w - hr1.y);

    int T = node >> 7, rr = node & 127;
    int c8 = lane >> 4;
    int g8 = (lane >> 1) & 7;
    int half = lane & 1;
    size_t base = ((size_t)T * 2 + c8) * 16384
                + SW128((uint32_t)(rr * 128 + g8 * 16)) + half * 8;
    *(uint2*)(g_ahi + base) = make_uint2(h0, h1);
    *(uint2*)(g_alo + base) = make_uint2(l0, l1);
}

#define TG_IDESC 0x8200490u

// ================== PASS 1: occ-1, B1 fully resident ==================
// raw y = A@W1 in TMEM (all 48 MMAs, single commit); RAW stats -> g_ssum/g_ssq.
// Pad rows are zero (zero_k). Cross-tile A prefetch overlaps stats epilogue.
#define P1_PTR   0
#define P1_MBAR  16
#define P1_PSUM  32       // 256 f
#define P1_PSQ   1056     // 256 f
#define P1_SSL   2080     // 256 f
#define P1_SQL   3104     // 256 f
#define P1_STAT  4128     // 64*66 f = 16896 B -> end 21024
#define P1_AHI   21504    // 32 KB (both chunks)
#define P1_ALO   54272    // 32 KB
#define P1_B1HI  87040    // 64 KB (both chunks)
#define P1_B1LO  152576   // 64 KB -> end 218112
#define P1_SMEM  218112

__global__ void __launch_bounds__(256, 1) pass1_k(
    const uint8_t* __restrict__ Ahi, const uint8_t* __restrict__ Alo,
    const __nv_bfloat16* __restrict__ B1hi, const __nv_bfloat16* __restrict__ B1lo,
    int ntiles)
{
    extern __shared__ char smem[];
    const uint32_t sb = smem_u32(smem);
    const int t = threadIdx.x, wid = t >> 5, lid = t & 31;
    float* psum = reinterpret_cast<float*>(smem + P1_PSUM);
    float* psq  = reinterpret_cast<float*>(smem + P1_PSQ);
    float* ssl  = reinterpret_cast<float*>(smem + P1_SSL);
    float* sql  = reinterpret_cast<float*>(smem + P1_SQL);
    float* statbuf = reinterpret_cast<float*>(smem + P1_STAT);   // [64][66]

    if (blockIdx.x == 0 && t < 128) {
        g_ssum2[t] = 0.f;
        g_ssq2[t]  = 0.f;
    }
    if (wid == 0) TC_ALLOC(sb + P1_PTR, 256);
    if (t == 0) MB_INIT(sb + P1_MBAR, 1);
    __syncthreads();
    uint32_t tmem;
    asm volatile("ld.shared.b32 %0, [%1];" : "=r"(tmem) : "r"(sb + P1_PTR));

    // ---- stage B1 fully (once): 4 chunk-images of 32 KB ----
#pragma unroll
    for (int it = 0; it < 8; it++) {
        int idx = t + it * 256;
        int r = idx >> 3, kg = idx & 7;
        uint32_t so = SW128((uint32_t)(r * 128 + kg * 16));
        const __nv_bfloat16* s0h = B1hi + (size_t)r * 128 + kg * 8;       // ch0
        const __nv_bfloat16* s1h = B1hi + (size_t)r * 128 + 64 + kg * 8;  // ch1
        const __nv_bfloat16* s0l = B1lo + (size_t)r * 128 + kg * 8;
        const __nv_bfloat16* s1l = B1lo + (size_t)r * 128 + 64 + kg * 8;
        CP_ASYNC16(sb + P1_B1HI + so,         s0h);
        CP_ASYNC16(sb + P1_B1HI + 32768 + so, s1h);
        CP_ASYNC16(sb + P1_B1LO + so,         s0l);
        CP_ASYNC16(sb + P1_B1LO + 32768 + so, s1l);
    }

#define P1_STAGE_A(TILE)                                                        \
    {                                                                           \
        size_t abase = (size_t)(TILE) * 32768;                                  \
        _Pragma("unroll")                                                       \
        for (int it = 0; it < 8; it++) {                                        \
            uint32_t o = (uint32_t)(t + it * 256) * 16;                         \
            CP_ASYNC16(sb + P1_AHI + o, Ahi + abase + o);                       \
            CP_ASYNC16(sb + P1_ALO + o, Alo + abase + o);                       \
        }                                                                       \
    }

    if (blockIdx.x < ntiles) P1_STAGE_A(blockIdx.x);
    CP_COMMIT();

    int pc = 0;
    for (int tile = blockIdx.x; tile < ntiles; tile += gridDim.x) {
        CP_WAIT0();
        FENCE_ASYNC();
        __syncthreads();
        // ---- all 48 MMAs, single commit ----
        if (wid == 0 && elect_one()) {
#pragma unroll
            for (int ch = 0; ch < 2; ch++) {
                uint64_t dA_h = make_desc(sb + P1_AHI + ch * 16384);
                uint64_t dA_l = make_desc(sb + P1_ALO + ch * 16384);
#pragma unroll
                for (int T = 0; T < 2; T++) {
                    uint64_t bh = make_desc(sb + P1_B1HI + ch * 32768) + T * 1024;
                    uint64_t bl = make_desc(sb + P1_B1LO + ch * 32768) + T * 1024;
                    uint32_t dt = tmem + T * 128;
#pragma unroll
                    for (int s = 0; s < 4; s++)
                        mma_bf16_ss(dt, dA_h + s * 2, bh + s * 2, TG_IDESC,
                                    (ch == 0 && s == 0) ? 0u : 1u);
#pragma unroll
                    for (int s = 0; s < 4; s++)
                        mma_bf16_ss(dt, dA_h + s * 2, bl + s * 2, TG_IDESC, 1u);
#pragma unroll
                    for (int s = 0; s < 4; s++)
                        mma_bf16_ss(dt, dA_l + s * 2, bh + s * 2, TG_IDESC, 1u);
                }
            }
            TC_COMMIT(sb + P1_MBAR);
        }
        MB_WAIT(sb + P1_MBAR, pc & 1); pc++;
        TC_FENCE_AFTER();

        // prefetch next tile's A (A smem free; overlaps epilogue)
        int nxt = tile + gridDim.x;
        if (nxt < ntiles) {
            __syncthreads();
            P1_STAGE_A(nxt);
            CP_COMMIT();
        }

        // ---- RAW y stats: 4 col-groups x 2 row-halves ----
        for (int pr = 0; pr < 4; pr++) {
#pragma unroll
            for (int rh = 0; rh < 2; rh++) {
                if (wid < 4 && (wid >> 1) == rh) {
                    uint32_t r0[32], r1[32];
                    LDTM32(r0, tmem + pr * 64);
                    LDTM32(r1, tmem + pr * 64 + 32);
                    TC_WAIT_LD();
                    int rl = (wid & 1) * 32 + lid;
#pragma unroll
                    for (int i = 0; i < 32; i++) {
                        statbuf[rl * 66 + i]      = __uint_as_float(r0[i]);
                        statbuf[rl * 66 + 32 + i] = __uint_as_float(r1[i]);
                    }
                }
                __syncthreads();
                {
                    int c = t & 63, h = t >> 6;   // h in 0..3, 16 rows each
                    float s = 0.f, q = 0.f;
#pragma unroll 8
                    for (int rr = 0; rr < 16; rr++) {
                        float v = statbuf[(h * 16 + rr) * 66 + c];
                        s += v;
                        q = fmaf(v, v, q);
                    }
                    psum[h * 64 + c] = s;
                    psq[h * 64 + c]  = q;
                }
                __syncthreads();
                if (t < 64) {
                    float s4 = psum[t] + psum[64 + t] + psum[128 + t] + psum[192 + t];
                    float q4 = psq[t]  + psq[64 + t]  + psq[128 + t]  + psq[192 + t];
                    if (rh == 0) { ssl[pr * 64 + t] = s4;  sql[pr * 64 + t] = q4; }
                    else         { ssl[pr * 64 + t] += s4; sql[pr * 64 + t] += q4; }
                }
                __syncthreads();
            }
        }
        if (wid < 4) TC_FENCE_BEFORE();
        __syncthreads();
        atomicAdd(&g_ssum[t], ssl[t]);
        atomicAdd(&g_ssq[t],  sql[t]);
        __syncthreads();
    }
#undef P1_STAGE_A

    CP_WAIT0();
    if (t == 0) MB_INVAL(sb + P1_MBAR);
    if (wid == 0) TC_DEALLOC(tmem, 256);
}

// ================== PASS 2 (R13 structure, occ 2) ==================
#define P_PTR   0
#define P_MBAR  16
#define P_SC    32
#define P_SH    1056
#define P_SB    2080
#define P_SSL   3104
#define P_SQL   4128
#define P_PSUM  5152
#define P_PSQ   6176
#define P_A1HI  8192
#define P_A1LO  24576
#define P_B1HI  40960
#define P_B1LO  73728
#define P_SMEM  106496

__global__ void __launch_bounds__(256, 2) pass2_k(
    const uint8_t* __restrict__ Ahi, const uint8_t* __restrict__ Alo,
    const __nv_bfloat16* __restrict__ B1hi, const __nv_bfloat16* __restrict__ B1lo,
    const __nv_bfloat16* __restrict__ B2hi, const __nv_bfloat16* __restrict__ B2lo,
    const float* __restrict__ b1, const float* __restrict__ b2,
    const float* __restrict__ g1, const float* __restrict__ be1, float invM,
    float* __restrict__ C, int M, int ntiles)
{
    extern __shared__ char smem[];
    const uint32_t sb = smem_u32(smem);
    const int t = threadIdx.x, wid = t >> 5, lid = t & 31;
    float* sSc = reinterpret_cast<float*>(smem + P_SC);
    float* sSh = reinterpret_cast<float*>(smem + P_SH);
    float* sB  = reinterpret_cast<float*>(smem + P_SB);
    float* ssl = reinterpret_cast<float*>(smem + P_SSL);
    float* sql = reinterpret_cast<float*>(smem + P_SQL);
    float* psum = reinterpret_cast<float*>(smem + P_PSUM);
    float* psq  = reinterpret_cast<float*>(smem + P_PSQ);
    float* statbuf = reinterpret_cast<float*>(smem + P_B1HI);

    if (wid == 0) TC_ALLOC(sb + P_PTR, 256);
    if (t == 0) MB_INIT(sb + P_MBAR, 1);
    {
        float mraw = g_ssum[t] * invM;
        float var  = g_ssq[t] * invM - mraw * mraw;
        float sc   = g1[t] * rsqrtf(var + 1e-5f);
        sSc[t] = sc;
        sSh[t] = fmaf(-mraw, sc, be1[t]);
        if (t < 128) sB[t] = b2[t];
    }
    __syncthreads();
    uint32_t tmem;
    asm volatile("ld.shared.b32 %0, [%1];" : "=r"(tmem) : "r"(sb + P_PTR));

    const uint64_t dA1hi = make_desc(sb + P_A1HI);
    const uint64_t dA1lo = make_desc(sb + P_A1LO);
    const uint64_t dB1hi = make_desc(sb + P_B1HI);
    const uint64_t dB1lo = make_desc(sb + P_B1LO);

    int pc = 0;

#define CPASYNC_A1(TILE, CH)                                                    \
    {                                                                           \
        size_t abase = ((size_t)(TILE) * 2 + (CH)) * 16384;                     \
        _Pragma("unroll")                                                       \
        for (int it = 0; it < 4; it++) {                                        \
            uint32_t o = (uint32_t)(t + it * 256) * 16;                         \
            CP_ASYNC16(sb + P_A1HI + o, Ahi + abase + o);                       \
            CP_ASYNC16(sb + P_A1LO + o, Alo + abase + o);                       \
        }                                                                       \
    }
#define CPASYNC_B1(CH)                                                          \
    {                                                                           \
        int kb_ = (CH) * 64;                                                    \
        _Pragma("unroll")                                                       \
        for (int it = 0; it < 8; it++) {                                        \
            int idx = t + it * 256;                                             \
            int r_ = idx >> 3, kg_ = idx & 7;                                   \
            uint32_t so_ = SW128((uint32_t)(r_ * 128 + kg_ * 16));              \
            size_t bo_ = (size_t)r_ * 128 + kb_ + kg_ * 8;                      \
            CP_ASYNC16(sb + P_B1HI + so_, B1hi + bo_);                          \
            CP_ASYNC16(sb + P_B1LO + so_, B1lo + bo_);                          \
        }                                                                       \
        CP_COMMIT();                                                            \
    }
#define MMA1_CHUNK(CH)                                                          \
    if (wid == 0 && elect_one()) {                                              \
        _Pragma("unroll")                                                       \
        for (int T = 0; T < 2; T++) {                                           \
            uint64_t bh = dB1hi + T * 1024;                                     \
            uint64_t bl = dB1lo + T * 1024;                                     \
            uint32_t dt = tmem + T * 128;                                       \
            _Pragma("unroll")                                                   \
            for (int s = 0; s < 4; s++)                                         \
                mma_bf16_ss(dt, dA1hi + s * 2, bh + s * 2, TG_IDESC,            \
                            ((CH) == 0 && s == 0) ? 0u : 1u);                   \
            _Pragma("unroll")                                                   \
            for (int s = 0; s < 4; s++)                                         \
                mma_bf16_ss(dt, dA1hi + s * 2, bl + s * 2, TG_IDESC, 1u);       \
            _Pragma("unroll")                                                   \
            for (int s = 0; s < 4; s++)                                         \
                mma_bf16_ss(dt, dA1lo + s * 2, bh + s * 2, TG_IDESC, 1u);       \
        }                                                                       \
        TC_COMMIT(sb + P_MBAR);                                                 \
    }

    for (int tile = blockIdx.x; tile < ntiles; tile += gridDim.x) {
        const int bm = tile * 128;

        // -------- phase 1: recompute y = A @ W1 --------
        CPASYNC_A1(tile, 0);
        CPASYNC_B1(0);
        CP_WAIT0();
        FENCE_ASYNC();
        __syncthreads();
        MMA1_CHUNK(0);
        MB_WAIT(sb + P_MBAR, pc & 1); pc++;
        CPASYNC_A1(tile, 1);
        CPASYNC_B1(1);
        CP_WAIT0();
        FENCE_ASYNC();
        __syncthreads();
        MMA1_CHUNK(1);
        MB_WAIT(sb + P_MBAR, pc & 1); pc++;
        TC_FENCE_AFTER();

        // -------- phase 2: h2 = bnrelu(y) @ W2 + b2 --------
        const uint64_t dB2hi = make_desc(sb + P_A1HI);
        const uint64_t dB2lo = make_desc(sb + P_A1LO);

#define CPASYNC_B2_HALF(CH)                                                     \
    {                                                                           \
        int kb_ = (CH) * 64;                                                    \
        _Pragma("unroll")                                                       \
        for (int it = 0; it < 8; it++) {                                        \
            int idx = (t - 128) + it * 128;                                     \
            int r_ = idx >> 3, kg_ = idx & 7;                                   \
            uint32_t so_ = SW128((uint32_t)(r_ * 128 + kg_ * 16));              \
            size_t bo_ = (size_t)r_ * 256 + kb_ + kg_ * 8;                      \
            CP_ASYNC16(sb + P_A1HI + so_, B2hi + bo_);                          \
            CP_ASYNC16(sb + P_A1LO + so_, B2lo + bo_);                          \
        }                                                                       \
        CP_COMMIT();                                                            \
        CP_WAIT0();                                                             \
    }
#define CPASYNC_B2_ALL(CH)                                                      \
    {                                                                           \
        int kb_ = (CH) * 64;                                                    \
        _Pragma("unroll")                                                       \
        for (int it = 0; it < 4; it++) {                                        \
            int idx = t + it * 256;                                             \
            int r_ = idx >> 3, kg_ = idx & 7;                                   \
            uint32_t so_ = SW128((uint32_t)(r_ * 128 + kg_ * 16));              \
            size_t bo_ = (size_t)r_ * 256 + kb_ + kg_ * 8;                      \
            CP_ASYNC16(sb + P_A1HI + so_, B2hi + bo_);                          \
            CP_ASYNC16(sb + P_A1LO + so_, B2lo + bo_);                          \
        }                                                                       \
        CP_COMMIT();                                                            \
        CP_WAIT0();                                                             \
    }
#define MMA2(SLOT, EN0)                                                         \
    if (wid == 0 && elect_one()) {                                              \
        uint64_t ah = make_desc(sb + P_B1HI + (SLOT) * 16384);                  \
        uint64_t al = make_desc(sb + P_B1LO + (SLOT) * 16384);                  \
        _Pragma("unroll")                                                       \
        for (int s = 0; s < 4; s++)                                             \
            mma_bf16_ss(tmem, ah + s * 2, dB2hi + s * 2, TG_IDESC,              \
                        ((EN0) && s == 0) ? 0u : 1u);                           \
        _Pragma("unroll")                                                       \
        for (int s = 0; s < 4; s++)                                             \
            mma_bf16_ss(tmem, ah + s * 2, dB2lo + s * 2, TG_IDESC, 1u);         \
        _Pragma("unroll")                                                       \
        for (int s = 0; s < 4; s++)                                             \
            mma_bf16_ss(tmem, al + s * 2, dB2hi + s * 2, TG_IDESC, 1u);         \
        TC_COMMIT(sb + P_MBAR);                                                 \
    }

#pragma unroll
        for (int half = 0; half < 2; half++) {
            if (wid < 4) {
                int r = wid * 32 + lid;
#pragma unroll
                for (int p2 = 0; p2 < 2; p2++) {
                    int b0 = half * 4 + p2 * 2;
                    uint32_t r0[32], r1[32];
                    LDTM32(r0, tmem + b0 * 32);
                    LDTM32(r1, tmem + (b0 + 1) * 32);
                    TC_WAIT_LD();
                    float v[64];
#pragma unroll
                    for (int i = 0; i < 32; i++) {
                        int c0 = b0 * 32 + i, c1 = (b0 + 1) * 32 + i;
                        v[i]      = fmaxf(fmaf(__uint_as_float(r0[i]), sSc[c0], sSh[c0]), 0.f);
                        v[32 + i] = fmaxf(fmaf(__uint_as_float(r1[i]), sSc[c1], sSh[c1]), 0.f);
                    }
#pragma unroll
                    for (int bb = 0; bb < 2; bb++) {
                        int blk = b0 + bb;
                        int slot = (blk >> 1) & 1;
                        const float* vv = v + bb * 32;
#pragma unroll
                        for (int q = 0; q < 4; q++) {
                            uint32_t h[4], lo[4];
#pragma unroll
                            for (int p = 0; p < 4; p++) {
                                float a0 = vv[q * 8 + p * 2], a1 = vv[q * 8 + p * 2 + 1];
                                h[p] = pack_bf16x2(a0, a1);
                                __nv_bfloat162 hb = *reinterpret_cast<__nv_bfloat162*>(&h[p]);
                                float2 hr = __bfloat1622float2(hb);
                                lo[p] = pack_bf16x2(a0 - hr.x, a1 - hr.y);
                            }
                            uint32_t so = SW128((uint32_t)(r * 128 + (blk & 1) * 64 + q * 16));
                            *(uint4*)(smem + P_B1HI + slot * 16384 + so) = make_uint4(h[0], h[1], h[2], h[3]);
                            *(uint4*)(smem + P_B1LO + slot * 16384 + so) = make_uint4(lo[0], lo[1], lo[2], lo[3]);
                        }
                    }
                }
                TC_FENCE_BEFORE();
            } else {
                CPASYNC_B2_HALF(2 * half);
            }
            FENCE_ASYNC();
            __syncthreads();
            MMA2(0, half == 0);
            MB_WAIT(sb + P_MBAR, pc & 1); pc++;
            CPASYNC_B2_ALL(2 * half + 1);
            FENCE_ASYNC();
            __syncthreads();
            MMA2(1, false);
            MB_WAIT(sb + P_MBAR, pc & 1); pc++;
            TC_FENCE_AFTER();
        }

#undef CPASYNC_B2_HALF
#undef CPASYNC_B2_ALL
#undef MMA2

        // -------- final epilogue: h2 --------
        for (int pr = 0; pr < 2; pr++) {
            if (wid < 4) {
                int r = wid * 32 + lid;
                int grow = bm + r;
                uint32_t r0[32], r1[32];
                LDTM32(r0, tmem + pr * 64);
                LDTM32(r1, tmem + pr * 64 + 32);
                TC_WAIT_LD();
                float v0[32], v1[32];
#pragma unroll
                for (int i = 0; i < 32; i++) {
                    v0[i] = __uint_as_float(r0[i]) + sB[pr * 64 + i];
                    v1[i] = __uint_as_float(r1[i]) + sB[pr * 64 + 32 + i];
                }
                if (grow < M) {
                    float* cp = C + (size_t)grow * 128 + pr * 64;
#pragma unroll
                    for (int q = 0; q < 8; q++) {
                        *(float4*)(cp + q * 4)      = *(float4*)(v0 + q * 4);
                        *(float4*)(cp + 32 + q * 4) = *(float4*)(v1 + q * 4);
                    }
                } else {
#pragma unroll
                    for (int i = 0; i < 32; i++) { v0[i] = 0.f; v1[i] = 0.f; }
                }
#pragma unroll
                for (int i = 0; i < 32; i++) {
                    statbuf[r * 66 + i]      = v0[i];
                    statbuf[r * 66 + 32 + i] = v1[i];
                }
            }
            __syncthreads();
            {
                int c = t & 63, h = t >> 6;
                float s = 0.f, q = 0.f;
#pragma unroll 8
                for (int rr = 0; rr < 32; rr++) {
                    float vv = statbuf[(h * 32 + rr) * 66 + c];
                    s += vv;
                    q = fmaf(vv, vv, q);
                }
                psum[h * 64 + c] = s;
                psq[h * 64 + c]  = q;
            }
            __syncthreads();
            if (t < 64) {
                ssl[pr * 64 + t] = psum[t] + psum[64 + t] + psum[128 + t] + psum[192 + t];
                sql[pr * 64 + t] = psq[t]  + psq[64 + t]  + psq[128 + t]  + psq[192 + t];
            }
            __syncthreads();
        }
        if (wid < 4) TC_FENCE_BEFORE();
        __syncthreads();
        if (t < 128) {
            atomicAdd(&g_ssum2[t], ssl[t]);
            atomicAdd(&g_ssq2[t],  sql[t]);
        }
        __syncthreads();
    }

#undef CPASYNC_A1
#undef CPASYNC_B1
#undef MMA1_CHUNK

    if (t == 0) MB_INVAL(sb + P_MBAR);
    if (wid == 0) TC_DEALLOC(tmem, 256);
}

// ---------------- readout pooling (computes outer BN inline) ----------------
__global__ void pool_k(const void* __restrict__ batch, int n,
                       const float* __restrict__ gamma, const float* __restrict__ beta,
                       float invM) {
    long long t = (long long)blockIdx.x * blockDim.x + threadIdx.x;
    long long i = t >> 5;
    if (i >= n) return;
    int lane = (int)(t & 31);
    long long g;
    if (g_i64flag) g = ((const long long*)batch)[i];
    else           g = (long long)((const int*)batch)[i];
    int c = lane * 4;
    float sc[4], sh[4];
#pragma unroll
    for (int j = 0; j < 4; j++) {
        float m   = g_ssum2[c + j] * invM;
        float var = g_ssq2[c + j] * invM - m * m;
        sc[j] = gamma[c + j] * rsqrtf(var + 1e-5f);
        sh[j] = beta[c + j] - m * sc[j];
    }
    float4 v = ((const float4*)g_h2)[i * 32 + lane];
    float r0 = fmaxf(fmaf(v.x, sc[0], sh[0]), 0.f);
    float r1 = fmaxf(fmaf(v.y, sc[1], sh[1]), 0.f);
    float r2 = fmaxf(fmaf(v.z, sc[2], sh[2]), 0.f);
    float r3 = fmaxf(fmaf(v.w, sc[3], sh[3]), 0.f);
    float* ps = g_ps + g * 128 + c;
    asm volatile("red.global.add.v4.f32 [%0], {%1, %2, %3, %4};"
                 :: "l"(ps), "f"(r0), "f"(r1), "f"(r2), "f"(r3) : "memory");
    unsigned int* mx = (unsigned int*)(g_pmx + g * 128 + c);
    atomicMax(mx + 0, __float_as_uint(r0));
    atomicMax(mx + 1, __float_as_uint(r1));
    atomicMax(mx + 2, __float_as_uint(r2));
    atomicMax(mx + 3, __float_as_uint(r3));
    if (lane == 0) atomicAdd(&g_cnt[g], 1.0f);
}

// ---------------- classifier ----------------
__global__ void cgemm1_k(const float* __restrict__ cW1, const float* __restrict__ cb1) {
    int g = blockIdx.x;
    int j = threadIdx.x;
    __shared__ float z[384];
    float cnt = fmaxf(g_cnt[g], 1.0f);
    float sv = g_ps[g * 128 + j];
    z[j]       = sv;
    z[128 + j] = sv / cnt;
    z[256 + j] = g_pmx[g * 128 + j];
    __syncthreads();
    float acc = cb1[j];
#pragma unroll 8
    for (int k = 0; k < 384; k++)
        acc = fmaf(z[k], cW1[k * 128 + j], acc);
    g_z1[g * 128 + j] = acc;
}

__global__ void cstats_k(const float* __restrict__ cg, const float* __restrict__ cbeta) {
    int j = threadIdx.x;
    float s = 0.f, q = 0.f;
    for (int g = 0; g < GCNT; g++) {
        float v = g_z1[g * 128 + j];
        s += v; q += v * v;
    }
    float m   = s * (1.0f / GCNT);
    float var = q * (1.0f / GCNT) - m * m;
    float sc  = cg[j] * rsqrtf(var + 1e-5f);
    g_scale[j] = sc;
    g_shift[j] = cbeta[j] - m * sc;
}

__global__ void chead_k(const float* __restrict__ cW2, const float* __restrict__ cb2,
                        const float* __restrict__ cW3, const float* __restrict__ cb3,
                        float* __restrict__ out) {
    int g = blockIdx.x;
    int j = threadIdx.x;
    __shared__ float a[128];
    __shared__ float z2[64];
    for (int k = j; k < 128; k += 64)
        a[k] = fmaxf(fmaf(g_z1[g * 128 + k], g_scale[k], g_shift[k]), 0.f);
    __syncthreads();
    float acc = cb2[j];
#pragma unroll 8
    for (int k = 0; k < 128; k++)
        acc = fmaf(a[k], cW2[k * 64 + j], acc);
    z2[j] = fmaxf(acc, 0.f);
    __syncthreads();
    if (j < 2) {
        float o = cb3[j];
#pragma unroll 8
        for (int k = 0; k < 64; k++)
            o = fmaf(z2[k], cW3[k * 2 + j], o);
        out[g * 2 + j] = o;
    }
}

// ---------------- launcher ----------------
extern "C" void kernel_launch(void* const* d_in, const int* in_sizes, int n_in,
                              void* d_out, int out_size) {
    const float* x     = (const float*)d_in[0];
    const void*  ei    = d_in[1];
    const void*  batch = d_in[2];
    int base = (in_sizes[3] == 1) ? 4 : 3;
    const float* W1    = (const float*)d_in[base + 0];
    const float* b1    = (const float*)d_in[base + 1];
    const float* g1    = (const float*)d_in[base + 2];
    const float* be1   = (const float*)d_in[base + 3];
    const float* W2    = (const float*)d_in[base + 4];
    const float* b2    = (const float*)d_in[base + 5];
    const float* gbn   = (const float*)d_in[base + 6];
    const float* bbn   = (const float*)d_in[base + 7];
    const float* eps   = (const float*)d_in[base + 8];
    const float* cW1   = (const float*)d_in[base + 9];
    const float* cb1   = (const float*)d_in[base + 10];
    const float* cg    = (const float*)d_in[base + 11];
    const float* cbeta = (const float*)d_in[base + 12];
    const float* cW2   = (const float*)d_in[base + 13];
    const float* cb2   = (const float*)d_in[base + 14];
    const float* cW3   = (const float*)d_in[base + 15];
    const float* cb3   = (const float*)d_in[base + 16];

    int n = in_sizes[0] / 128;
    long long E = (long long)in_sizes[1] / 2;
    int n32 = n * 32;
    int nb = (n32 + 255) / 256;
    int gx = (n + 127) / 128;
    int p1grid = (gx < 148) ? gx : 148;
    int p2grid = (gx < 296) ? gx : 296;
    int eblk = (int)((E + 255) / 256);
    int nscan = (n + 1023) / 1024;
    int ablk = (n * 32 + 255) / 256;
    float invM = 1.0f / (float)n;

    static int smem_set = 0;
    if (!smem_set) {
        cudaFuncSetAttribute(pass1_k, cudaFuncAttributeMaxDynamicSharedMemorySize, P1_SMEM);
        cudaFuncSetAttribute(pass2_k, cudaFuncAttributeMaxDynamicSharedMemorySize, P_SMEM);
        smem_set = 1;
    }

    float *p_h2;
    uint8_t *p_ahi, *p_alo;
    __nv_bfloat16 *p_b1hi, *p_b1lo, *p_b2hi, *p_b2lo;
    cudaGetSymbolAddress((void**)&p_h2,  g_h2);
    cudaGetSymbolAddress((void**)&p_ahi, g_ahi);
    cudaGetSymbolAddress((void**)&p_alo, g_alo);
    cudaGetSymbolAddress((void**)&p_b1hi, g_b1hi);
    cudaGetSymbolAddress((void**)&p_b1lo, g_b1lo);
    cudaGetSymbolAddress((void**)&p_b2hi, g_b2hi);
    cudaGetSymbolAddress((void**)&p_b2lo, g_b2lo);

    detect_k<<<1, 1>>>((const unsigned int*)ei);
    wconv_k<<<(NLAYER * 256 * 128 + 255) / 256, 256>>>(W1, W2);
    zero_k<<<512, 256>>>(n, gx);

    // CSR build (once; edges shared by all layers)
    count_k<<<eblk, 256>>>(ei, E);
    scanA_k<<<nscan, 256>>>(n);
    scanB_k<<<1, 32>>>(nscan);
    scanC_k<<<nscan, 256>>>(n);
    fill_k<<<eblk, 256>>>(ei, E);

    for (int l = 0; l < 4; l++) {
        if (l == 0)
            agg_k<false><<<ablk, 256>>>(x, eps, l, n, nullptr, nullptr, invM);
        else
            agg_k<true><<<ablk, 256>>>(p_h2, eps, l, n,
                                       gbn + (l - 1) * 128, bbn + (l - 1) * 128, invM);

        pass1_k<<<p1grid, 256, P1_SMEM>>>(
            p_ahi, p_alo,
            p_b1hi + (size_t)l * 32768, p_b1lo + (size_t)l * 32768, gx);
        pass2_k<<<p2grid, 256, P_SMEM>>>(
            p_ahi, p_alo,
            p_b1hi + (size_t)l * 32768, p_b1lo + (size_t)l * 32768,
            p_b2hi + (size_t)l * 32768, p_b2lo + (size_t)l * 32768,
            b1 + l * 256, b2 + l * 128, g1 + l * 256, be1 + l * 256, invM,
            p_h2, n, gx);
    }

    pool_k<<<nb, 256>>>(batch, n, gbn + 3 * 128, bbn + 3 * 128, invM);
    cgemm1_k<<<GCNT, 128>>>(cW1, cb1);
    cstats_k<<<1, 128>>>(cg, cbeta);
    chead_k<<<GCNT, 64>>>(cW2, cb2, cW3, cb3, (float*)d_out);
}

// round 16
// speedup vs baseline: 1.0594x; 1.0340x over previous
#include <cuda_runtime.h>
#include <cuda_bf16.h>
#include <cstdint>
#include <cstddef>

// Problem constants (fixed shapes)
#define NMAX 100000
#define EMAX 500000
#define GCNT 512
#define NLAYER 4
#define NTILE ((NMAX + 127) / 128)   // 782

// tcgen05 only exists in the arch-specific (sm_103a) device pass.
#if defined(__CUDA_ARCH__) && defined(__CUDA_ARCH_FEAT_SM103_ALL)
#define HAS_TC 1
#else
#define HAS_TC 0
#endif

// ---------------- device scratch ----------------
__device__ float g_h2 [NMAX * 128];
// aggregated layer input, pre-split bf16 hi/lo, pre-swizzled smem image:
// [tile][chunk(2)][16KB image]  where image[SW128(row*128 + kg*16)]
__device__ uint8_t g_ahi[(size_t)NTILE * 32768];
__device__ uint8_t g_alo[(size_t)NTILE * 32768];
__device__ float g_ssum [256];
__device__ float g_ssq  [256];
__device__ float g_ssum2[128];
__device__ float g_ssq2 [128];
__device__ float g_scale[256];   // used by classifier only now
__device__ float g_shift[256];
__device__ float g_ps [GCNT * 128];
__device__ float g_pmx[GCNT * 128];
__device__ float g_cnt[GCNT];
__device__ float g_z1 [GCNT * 128];
__device__ int   g_i64flag;

// CSR (built once per launch; edges fixed across layers)
__device__ int g_deg [NMAX];
__device__ int g_off [NMAX];
__device__ int g_cur [NMAX];
__device__ int g_csr [EMAX];
__device__ int g_bsum[128];
__device__ int g_bscn[128];

// pre-split weights, B layout: [layer][n(out)][k(in)] bf16, K-major rows
__device__ __nv_bfloat16 g_b1hi[NLAYER * 256 * 128];
__device__ __nv_bfloat16 g_b1lo[NLAYER * 256 * 128];
__device__ __nv_bfloat16 g_b2hi[NLAYER * 128 * 256];
__device__ __nv_bfloat16 g_b2lo[NLAYER * 128 * 256];

// ---------------- PTX helpers ----------------
__device__ __forceinline__ uint32_t smem_u32(const void* p) {
    uint32_t a;
    asm("{ .reg .u64 t; cvta.to.shared.u64 t, %1; cvt.u32.u64 %0, t; }" : "=r"(a) : "l"(p));
    return a;
}
__device__ __forceinline__ uint32_t elect_one() {
    uint32_t p;
    asm volatile("{ .reg .pred p; elect.sync _|p, 0xFFFFFFFF; selp.b32 %0, 1, 0, p; }" : "=r"(p));
    return p;
}
#define SW128(o) ((o) ^ (((o) >> 3) & 0x70))
static __device__ __forceinline__ uint64_t make_desc(uint32_t addr) {
    return ((uint64_t)2 << 61) | ((uint64_t)1 << 46) | ((uint64_t)64 << 32) |
           ((uint64_t)1 << 16) | ((uint64_t)(addr >> 4) & 0x3FFF);
}

#if HAS_TC
__device__ __forceinline__ void mma_bf16_ss(uint32_t d, uint64_t a, uint64_t b,
                                            uint32_t idesc, uint32_t en) {
    asm volatile(
        "{\n\t.reg .pred p;\n\tsetp.ne.u32 p, %4, 0;\n\t"
        "tcgen05.mma.cta_group::1.kind::f16 [%0], %1, %2, %3, {%5, %5, %5, %5}, p;\n\t}"
        :: "r"(d), "l"(a), "l"(b), "r"(idesc), "r"(en), "r"(0u) : "memory");
}
#define TC_ALLOC(sm, n)  asm volatile("tcgen05.alloc.cta_group::1.sync.aligned.shared::cta.b32 [%0], %1;" :: "r"(sm), "r"((uint32_t)(n)) : "memory")
#define TC_DEALLOC(t, n) asm volatile("tcgen05.dealloc.cta_group::1.sync.aligned.b32 %0, %1;" :: "r"(t), "r"((uint32_t)(n)))
#define TC_COMMIT(mb)    asm volatile("tcgen05.commit.cta_group::1.mbarrier::arrive::one.shared::cluster.b64 [%0];" :: "r"(mb) : "memory")
#define TC_FENCE_AFTER() asm volatile("tcgen05.fence::after_thread_sync;" ::: "memory")
#define TC_FENCE_BEFORE() asm volatile("tcgen05.fence::before_thread_sync;" ::: "memory")
#define TC_WAIT_LD()     asm volatile("tcgen05.wait::ld.sync.aligned;" ::: "memory")
#define LDTM32(r, a)                                                            \
    asm volatile("tcgen05.ld.sync.aligned.32x32b.x32.b32 "                      \
        "{%0,%1,%2,%3,%4,%5,%6,%7,%8,%9,%10,%11,%12,%13,%14,%15,"               \
        "%16,%17,%18,%19,%20,%21,%22,%23,%24,%25,%26,%27,%28,%29,%30,%31}, [%32];" \
        : "=r"((r)[0]),"=r"((r)[1]),"=r"((r)[2]),"=r"((r)[3]),                  \
          "=r"((r)[4]),"=r"((r)[5]),"=r"((r)[6]),"=r"((r)[7]),                  \
          "=r"((r)[8]),"=r"((r)[9]),"=r"((r)[10]),"=r"((r)[11]),                \
          "=r"((r)[12]),"=r"((r)[13]),"=r"((r)[14]),"=r"((r)[15]),              \
          "=r"((r)[16]),"=r"((r)[17]),"=r"((r)[18]),"=r"((r)[19]),              \
          "=r"((r)[20]),"=r"((r)[21]),"=r"((r)[22]),"=r"((r)[23]),              \
          "=r"((r)[24]),"=r"((r)[25]),"=r"((r)[26]),"=r"((r)[27]),              \
          "=r"((r)[28]),"=r"((r)[29]),"=r"((r)[30]),"=r"((r)[31])               \
        : "r"(a))
#define MB_WAIT(mb, par) do {                                                   \
    uint32_t _m = (mb), _p = (par), _d;                                         \
    asm volatile("{ .reg .pred p; mbarrier.try_wait.parity.acquire.cta.shared::cta.b64 p, [%1], %2; selp.b32 %0, 1, 0, p; }" \
                 : "=r"(_d) : "r"(_m), "r"(_p) : "memory");                     \
    if (!_d) {                                                                  \
        asm volatile("{ .reg .pred P1; W%=: mbarrier.try_wait.parity.acquire.cta.shared::cta.b64 P1, [%0], %1, 0x989680; @P1 bra.uni D%=; bra.uni W%=; D%=: }" \
                     :: "r"(_m), "r"(_p) : "memory");                           \
    }                                                                           \
} while (0)
#else
__device__ __forceinline__ void mma_bf16_ss(uint32_t, uint64_t, uint64_t, uint32_t, uint32_t) {}
#define TC_ALLOC(sm, n)   ((void)0)
#define TC_DEALLOC(t, n)  ((void)0)
#define TC_COMMIT(mb)     ((void)0)
#define TC_FENCE_AFTER()  ((void)0)
#define TC_FENCE_BEFORE() ((void)0)
#define TC_WAIT_LD()      ((void)0)
#define LDTM32(r, a)      do { _Pragma("unroll") for (int _i = 0; _i < 32; _i++) (r)[_i] = 0u; } while (0)
#define MB_WAIT(mb, par)  ((void)0)
#endif

#define MB_INIT(mb, c)   asm volatile("mbarrier.init.shared.b64 [%0], %1;" :: "r"(mb), "r"((uint32_t)(c)) : "memory")
#define MB_INVAL(mb)     asm volatile("mbarrier.inval.shared.b64 [%0];" :: "r"(mb) : "memory")
#define FENCE_ASYNC()    asm volatile("fence.proxy.async.shared::cta;" ::: "memory")
#define CP_ASYNC16(dst, src) asm volatile("cp.async.ca.shared.global [%0], [%1], 16;" :: "r"(dst), "l"(src) : "memory")
#define CP_COMMIT()      asm volatile("cp.async.commit_group;" ::: "memory")
#define CP_WAIT0()       asm volatile("cp.async.wait_group 0;" ::: "memory")

// ---------------- dtype detection ----------------
__global__ void detect_k(const unsigned int* __restrict__ e) {
    unsigned acc = 0;
    for (int i = 1; i < 128; i += 2) acc |= e[i];
    g_i64flag = (acc == 0u) ? 1 : 0;
}

// ---------------- weight split fp32 -> bf16 hi/lo ----------------
__global__ void wconv_k(const float* __restrict__ W1, const float* __restrict__ W2) {
    int i = blockIdx.x * 256 + threadIdx.x;
    const int tot = NLAYER * 256 * 128;
    if (i >= tot) return;
    int l = i / (256 * 128), rem = i % (256 * 128);
    {
        int n = rem / 128, k = rem % 128;
        float w = W1[l * 32768 + k * 256 + n];
        __nv_bfloat16 h = __float2bfloat16(w);
        g_b1hi[i] = h;
        g_b1lo[i] = __float2bfloat16(w - __bfloat162float(h));
    }
    {
        int n = rem / 256, k = rem % 256;
        float w = W2[l * 32768 + k * 128 + n];
        __nv_bfloat16 h = __float2bfloat16(w);
        g_b2hi[i] = h;
        g_b2lo[i] = __float2bfloat16(w - __bfloat162float(h));
    }
}

// ---------------- zero (grid-stride; covers n + pad tile image) ----------------
__global__ void zero_k(int n, int gx) {
    int tot = (n > GCNT * 128) ? n : GCNT * 128;
    for (int i = blockIdx.x * blockDim.x + threadIdx.x; i < tot;
         i += gridDim.x * blockDim.x) {
        if (i < 256) { g_ssum[i] = 0.f; g_ssq[i] = 0.f; }
        if (i < 128) { g_ssum2[i] = 0.f; g_ssq2[i] = 0.f; }
        if (i < GCNT * 128) { g_ps[i] = 0.f; g_pmx[i] = 0.f; }
        if (i < GCNT) g_cnt[i] = 0.f;
        if (i < n) g_deg[i] = 0;
    }
    size_t lt = (size_t)(gx - 1) * 32768;
    for (int i = blockIdx.x * blockDim.x + threadIdx.x; i < 32768 / 16;
         i += gridDim.x * blockDim.x) {
        ((uint4*)(g_ahi + lt))[i] = make_uint4(0, 0, 0, 0);
        ((uint4*)(g_alo + lt))[i] = make_uint4(0, 0, 0, 0);
    }
}

// ---------------- CSR build ----------------
__global__ void count_k(const void* __restrict__ ei, long long E) {
    long long e = (long long)blockIdx.x * blockDim.x + threadIdx.x;
    if (e >= E) return;
    int d;
    if (g_i64flag) d = (int)((const long long*)ei)[E + e];
    else           d = ((const int*)ei)[E + e];
    atomicAdd(&g_deg[d], 1);
}

__global__ void scanA_k(int n) {
    __shared__ int sred[256];
    int blk = blockIdx.x, t = threadIdx.x;
    int base = blk * 1024 + t * 4;
    int s = 0;
#pragma unroll
    for (int j = 0; j < 4; j++) {
        int idx = base + j;
        if (idx < n) s += g_deg[idx];
    }
    sred[t] = s;
    __syncthreads();
    for (int o = 128; o > 0; o >>= 1) {
        if (t < o) sred[t] += sred[t + o];
        __syncthreads();
    }
    if (t == 0) g_bsum[blk] = sred[0];
}

__global__ void scanB_k(int nblk) {
    if (threadIdx.x == 0) {
        int run = 0;
        for (int i = 0; i < nblk; i++) { g_bscn[i] = run; run += g_bsum[i]; }
    }
}

__global__ void scanC_k(int n) {
    __shared__ int sth[256];
    int blk = blockIdx.x, t = threadIdx.x;
    int base = blk * 1024 + t * 4;
    int v[4];
    int s = 0;
#pragma unroll
    for (int j = 0; j < 4; j++) {
        int idx = base + j;
        v[j] = (idx < n) ? g_deg[idx] : 0;
        s += v[j];
    }
    sth[t] = s;
    __syncthreads();
    for (int o = 1; o < 256; o <<= 1) {
        int add = (t >= o) ? sth[t - o] : 0;
        __syncthreads();
        sth[t] += add;
        __syncthreads();
    }
    int tpre = (t > 0 ? sth[t - 1] : 0) + g_bscn[blk];
#pragma unroll
    for (int j = 0; j < 4; j++) {
        int idx = base + j;
        if (idx < n) { g_off[idx] = tpre; g_cur[idx] = tpre; }
        tpre += v[j];
    }
}

__global__ void fill_k(const void* __restrict__ ei, long long E) {
    long long e = (long long)blockIdx.x * blockDim.x + threadIdx.x;
    if (e >= E) return;
    int s, d;
    if (g_i64flag) {
        const long long* p = (const long long*)ei;
        s = (int)p[e]; d = (int)p[E + e];
    } else {
        const int* p = (const int*)ei;
        s = p[e]; d = p[E + e];
    }
    int pos = atomicAdd(&g_cur[d], 1);
    if (pos < EMAX) g_csr[pos] = s;
}

__device__ __forceinline__ uint32_t pack_bf16x2(float a, float b) {
    __nv_bfloat162 h = __float22bfloat162_rn(make_float2(a, b));
    return *reinterpret_cast<uint32_t*>(&h);
}

// ---------------- CSR aggregation + bf16 split + swizzled store ----------------
template<bool BN>
__global__ void __launch_bounds__(256) agg_k(
    const float* __restrict__ SRC, const float* __restrict__ epsp, int l, int n,
    const float* __restrict__ gamma, const float* __restrict__ beta, float invM) {
    if (BN && blockIdx.x == 0) {
        g_ssum[threadIdx.x] = 0.f;
        g_ssq[threadIdx.x]  = 0.f;
    }
    int node = (int)(((long long)blockIdx.x * blockDim.x + threadIdx.x) >> 5);
    int lane = threadIdx.x & 31;
    if (node >= n) return;
    float e = 1.0f + epsp[l];

    float sc0, sc1, sc2, sc3, sh0, sh1, sh2, sh3;
    if (BN) {
        int c = lane * 4;
#pragma unroll
        for (int j = 0; j < 4; j++) {
            float m   = g_ssum2[c + j] * invM;
            float var = g_ssq2[c + j] * invM - m * m;
            float sc  = gamma[c + j] * rsqrtf(var + 1e-5f);
            float sh  = beta[c + j] - m * sc;
            if (j == 0) { sc0 = sc; sh0 = sh; }
            else if (j == 1) { sc1 = sc; sh1 = sh; }
            else if (j == 2) { sc2 = sc; sh2 = sh; }
            else { sc3 = sc; sh3 = sh; }
        }
    }
#define FBN(v)                                                                   \
    if (BN) {                                                                    \
        v.x = fmaxf(fmaf(v.x, sc0, sh0), 0.f);                                   \
        v.y = fmaxf(fmaf(v.y, sc1, sh1), 0.f);                                   \
        v.z = fmaxf(fmaf(v.z, sc2, sh2), 0.f);                                   \
        v.w = fmaxf(fmaf(v.w, sc3, sh3), 0.f);                                   \
    }

    int beg = g_off[node];
    int deg = g_deg[node];

    float4 self = ((const float4*)SRC)[(size_t)node * 32 + lane];
    FBN(self);
    float4 a0 = make_float4(self.x * e, self.y * e, self.z * e, self.w * e);
    float4 a1 = make_float4(0.f, 0.f, 0.f, 0.f);
    float4 a2 = make_float4(0.f, 0.f, 0.f, 0.f);
    float4 a3 = make_float4(0.f, 0.f, 0.f, 0.f);

    int i = 0;
    for (; i + 4 <= deg; i += 4) {
        int s0 = g_csr[beg + i];
        int s1 = g_csr[beg + i + 1];
        int s2 = g_csr[beg + i + 2];
        int s3 = g_csr[beg + i + 3];
        float4 v0 = ((const float4*)SRC)[(size_t)s0 * 32 + lane];
        float4 v1 = ((const float4*)SRC)[(size_t)s1 * 32 + lane];
        float4 v2 = ((const float4*)SRC)[(size_t)s2 * 32 + lane];
        float4 v3 = ((const float4*)SRC)[(size_t)s3 * 32 + lane];
        FBN(v0); FBN(v1); FBN(v2); FBN(v3);
        a0.x += v0.x; a0.y += v0.y; a0.z += v0.z; a0.w += v0.w;
        a1.x += v1.x; a1.y += v1.y; a1.z += v1.z; a1.w += v1.w;
        a2.x += v2.x; a2.y += v2.y; a2.z += v2.z; a2.w += v2.w;
        a3.x += v3.x; a3.y += v3.y; a3.z += v3.z; a3.w += v3.w;
    }
    if (i < deg) {
        int rem = deg - i;
        int s0 = g_csr[beg + i];
        int s1 = g_csr[beg + ((rem > 1) ? i + 1 : i)];
        int s2 = g_csr[beg + ((rem > 2) ? i + 2 : i)];
        float4 v0 = ((const float4*)SRC)[(size_t)s0 * 32 + lane];
        float4 v1 = ((const float4*)SRC)[(size_t)s1 * 32 + lane];
        float4 v2 = ((const float4*)SRC)[(size_t)s2 * 32 + lane];
        FBN(v0); FBN(v1); FBN(v2);
        a1.x += v0.x; a1.y += v0.y; a1.z += v0.z; a1.w += v0.w;
        if (rem > 1) { a2.x += v1.x; a2.y += v1.y; a2.z += v1.z; a2.w += v1.w; }
        if (rem > 2) { a3.x += v2.x; a3.y += v2.y; a3.z += v2.z; a3.w += v2.w; }
    }
#undef FBN
    float4 r;
    r.x = (a0.x + a1.x) + (a2.x + a3.x);
    r.y = (a0.y + a1.y) + (a2.y + a3.y);
    r.z = (a0.z + a1.z) + (a2.z + a3.z);
    r.w = (a0.w + a1.w) + (a2.w + a3.w);

    uint32_t h0 = pack_bf16x2(r.x, r.y);
    uint32_t h1 = pack_bf16x2(r.z, r.w);
    __nv_bfloat162 hb0 = *reinterpret_cast<__nv_bfloat162*>(&h0);
    __nv_bfloat162 hb1 = *reinterpret_cast<__nv_bfloat162*>(&h1);
    float2 hr0 = __bfloat1622float2(hb0);
    float2 hr1 = __bfloat1622float2(hb1);
    uint32_t l0 = pack_bf16x2(r.x - hr0.x, r.y - hr0.y);
    uint32_t l1 = pack_bf16x2(r.z - hr1.x, r.w - hr1.y);

    int T = node >> 7, rr = node & 127;
    int c8 = lane >> 4;
    int g8 = (lane >> 1) & 7;
    int half = lane & 1;
    size_t base = ((size_t)T * 2 + c8) * 16384
                + SW128((uint32_t)(rr * 128 + g8 * 16)) + half * 8;
    *(uint2*)(g_ahi + base) = make_uint2(h0, h1);
    *(uint2*)(g_alo + base) = make_uint2(l0, l1);
}

#define TG_IDESC 0x8200490u

// ================== PASS 1: occ-1, B1 fully resident ==================
#define P1_PTR   0
#define P1_MBAR  16
#define P1_PSUM  32
#define P1_PSQ   1056
#define P1_SSL   2080
#define P1_SQL   3104
#define P1_STAT  4128     // 64*66 f -> end 21024
#define P1_AHI   21504
#define P1_ALO   54272
#define P1_B1HI  87040
#define P1_B1LO  152576
#define P1_SMEM  218112

__global__ void __launch_bounds__(256, 1) pass1_k(
    const uint8_t* __restrict__ Ahi, const uint8_t* __restrict__ Alo,
    const __nv_bfloat16* __restrict__ B1hi, const __nv_bfloat16* __restrict__ B1lo,
    int ntiles)
{
    extern __shared__ char smem[];
    const uint32_t sb = smem_u32(smem);
    const int t = threadIdx.x, wid = t >> 5, lid = t & 31;
    float* psum = reinterpret_cast<float*>(smem + P1_PSUM);
    float* psq  = reinterpret_cast<float*>(smem + P1_PSQ);
    float* ssl  = reinterpret_cast<float*>(smem + P1_SSL);
    float* sql  = reinterpret_cast<float*>(smem + P1_SQL);
    float* statbuf = reinterpret_cast<float*>(smem + P1_STAT);

    if (blockIdx.x == 0 && t < 128) {
        g_ssum2[t] = 0.f;
        g_ssq2[t]  = 0.f;
    }
    if (wid == 0) TC_ALLOC(sb + P1_PTR, 256);
    if (t == 0) MB_INIT(sb + P1_MBAR, 1);
    __syncthreads();
    uint32_t tmem;
    asm volatile("ld.shared.b32 %0, [%1];" : "=r"(tmem) : "r"(sb + P1_PTR));

#pragma unroll
    for (int it = 0; it < 8; it++) {
        int idx = t + it * 256;
        int r = idx >> 3, kg = idx & 7;
        uint32_t so = SW128((uint32_t)(r * 128 + kg * 16));
        CP_ASYNC16(sb + P1_B1HI + so,         B1hi + (size_t)r * 128 + kg * 8);
        CP_ASYNC16(sb + P1_B1HI + 32768 + so, B1hi + (size_t)r * 128 + 64 + kg * 8);
        CP_ASYNC16(sb + P1_B1LO + so,         B1lo + (size_t)r * 128 + kg * 8);
        CP_ASYNC16(sb + P1_B1LO + 32768 + so, B1lo + (size_t)r * 128 + 64 + kg * 8);
    }

#define P1_STAGE_A(TILE)                                                        \
    {                                                                           \
        size_t abase = (size_t)(TILE) * 32768;                                  \
        _Pragma("unroll")                                                       \
        for (int it = 0; it < 8; it++) {                                        \
            uint32_t o = (uint32_t)(t + it * 256) * 16;                         \
            CP_ASYNC16(sb + P1_AHI + o, Ahi + abase + o);                       \
            CP_ASYNC16(sb + P1_ALO + o, Alo + abase + o);                       \
        }                                                                       \
    }

    if (blockIdx.x < ntiles) P1_STAGE_A(blockIdx.x);
    CP_COMMIT();

    int pc = 0;
    for (int tile = blockIdx.x; tile < ntiles; tile += gridDim.x) {
        CP_WAIT0();
        FENCE_ASYNC();
        __syncthreads();
        if (wid == 0 && elect_one()) {
#pragma unroll
            for (int ch = 0; ch < 2; ch++) {
                uint64_t dA_h = make_desc(sb + P1_AHI + ch * 16384);
                uint64_t dA_l = make_desc(sb + P1_ALO + ch * 16384);
#pragma unroll
                for (int T = 0; T < 2; T++) {
                    uint64_t bh = make_desc(sb + P1_B1HI + ch * 32768) + T * 1024;
                    uint64_t bl = make_desc(sb + P1_B1LO + ch * 32768) + T * 1024;
                    uint32_t dt = tmem + T * 128;
#pragma unroll
                    for (int s = 0; s < 4; s++)
                        mma_bf16_ss(dt, dA_h + s * 2, bh + s * 2, TG_IDESC,
                                    (ch == 0 && s == 0) ? 0u : 1u);
#pragma unroll
                    for (int s = 0; s < 4; s++)
                        mma_bf16_ss(dt, dA_h + s * 2, bl + s * 2, TG_IDESC, 1u);
#pragma unroll
                    for (int s = 0; s < 4; s++)
                        mma_bf16_ss(dt, dA_l + s * 2, bh + s * 2, TG_IDESC, 1u);
                }
            }
            TC_COMMIT(sb + P1_MBAR);
        }
        MB_WAIT(sb + P1_MBAR, pc & 1); pc++;
        TC_FENCE_AFTER();

        int nxt = tile + gridDim.x;
        if (nxt < ntiles) {
            __syncthreads();
            P1_STAGE_A(nxt);
            CP_COMMIT();
        }

        for (int pr = 0; pr < 4; pr++) {
#pragma unroll
            for (int rh = 0; rh < 2; rh++) {
                if (wid < 4 && (wid >> 1) == rh) {
                    uint32_t r0[32], r1[32];
                    LDTM32(r0, tmem + pr * 64);
                    LDTM32(r1, tmem + pr * 64 + 32);
                    TC_WAIT_LD();
                    int rl = (wid & 1) * 32 + lid;
#pragma unroll
                    for (int i = 0; i < 32; i++) {
                        statbuf[rl * 66 + i]      = __uint_as_float(r0[i]);
                        statbuf[rl * 66 + 32 + i] = __uint_as_float(r1[i]);
                    }
                }
                __syncthreads();
                {
                    int c = t & 63, h = t >> 6;
                    float s = 0.f, q = 0.f;
#pragma unroll 8
                    for (int rr = 0; rr < 16; rr++) {
                        float v = statbuf[(h * 16 + rr) * 66 + c];
                        s += v;
                        q = fmaf(v, v, q);
                    }
                    psum[h * 64 + c] = s;
                    psq[h * 64 + c]  = q;
                }
                __syncthreads();
                if (t < 64) {
                    float s4 = psum[t] + psum[64 + t] + psum[128 + t] + psum[192 + t];
                    float q4 = psq[t]  + psq[64 + t]  + psq[128 + t]  + psq[192 + t];
                    if (rh == 0) { ssl[pr * 64 + t] = s4;  sql[pr * 64 + t] = q4; }
                    else         { ssl[pr * 64 + t] += s4; sql[pr * 64 + t] += q4; }
                }
                __syncthreads();
            }
        }
        if (wid < 4) TC_FENCE_BEFORE();
        __syncthreads();
        atomicAdd(&g_ssum[t], ssl[t]);
        atomicAdd(&g_ssq[t],  sql[t]);
        __syncthreads();
    }
#undef P1_STAGE_A

    CP_WAIT0();
    if (t == 0) MB_INVAL(sb + P1_MBAR);
    if (wid == 0) TC_DEALLOC(tmem, 256);
}

// ================== PASS 2: occ-1, big-buffer, few-commit ==================
// phase1: A (both chunks) + B1 (both chunks) staged -> 48 MMAs single commit -> y
// phase2: per 128-col half: A2 2 chunks into B1 region (dead) + B2 2 chunks into
//         A region (dead); 24 MMAs single commit. h2 epilogue w/ 64-row statbuf.
#define Q_PTR   0
#define Q_MBAR  16
#define Q_SC    32      // 256 f
#define Q_SH    1056    // 256 f
#define Q_SB    2080    // 128 f
#define Q_SSL   2592    // 128 f
#define Q_SQL   3104    // 128 f
#define Q_PSUM  3616    // 256 f
#define Q_PSQ   4640    // 256 f -> 5664
#define Q_A     8192    // A: hi ch0@+0, ch1@+16384; lo@+32768,+49152 (64 KB)
                        // phase2: B2 hi buf0@+0, buf1@+16384; lo@+32768,+49152
#define Q_B1HI  73728   // ch0@+0, ch1@+32768 (64 KB); phase2: A2HI slot s@+s*16384
#define Q_B1LO  139264  // ch0@+0, ch1@+32768 (64 KB); phase2: A2LO slot s@+s*16384
#define Q_STAT  204800  // 64*66 f = 16896 -> end 221696
#define Q_SMEM  221696

__global__ void __launch_bounds__(256, 1) pass2_k(
    const uint8_t* __restrict__ Ahi, const uint8_t* __restrict__ Alo,
    const __nv_bfloat16* __restrict__ B1hi, const __nv_bfloat16* __restrict__ B1lo,
    const __nv_bfloat16* __restrict__ B2hi, const __nv_bfloat16* __restrict__ B2lo,
    const float* __restrict__ b1, const float* __restrict__ b2,
    const float* __restrict__ g1, const float* __restrict__ be1, float invM,
    float* __restrict__ C, int M, int ntiles)
{
    extern __shared__ char smem[];
    const uint32_t sb = smem_u32(smem);
    const int t = threadIdx.x, wid = t >> 5, lid = t & 31;
    float* sSc = reinterpret_cast<float*>(smem + Q_SC);
    float* sSh = reinterpret_cast<float*>(smem + Q_SH);
    float* sB  = reinterpret_cast<float*>(smem + Q_SB);
    float* ssl = reinterpret_cast<float*>(smem + Q_SSL);
    float* sql = reinterpret_cast<float*>(smem + Q_SQL);
    float* psum = reinterpret_cast<float*>(smem + Q_PSUM);
    float* psq  = reinterpret_cast<float*>(smem + Q_PSQ);
    float* statbuf = reinterpret_cast<float*>(smem + Q_STAT);

    if (wid == 0) TC_ALLOC(sb + Q_PTR, 256);
    if (t == 0) MB_INIT(sb + Q_MBAR, 1);
    {
        float mraw = g_ssum[t] * invM;
        float var  = g_ssq[t] * invM - mraw * mraw;
        float sc   = g1[t] * rsqrtf(var + 1e-5f);
        sSc[t] = sc;
        sSh[t] = fmaf(-mraw, sc, be1[t]);
        if (t < 128) sB[t] = b2[t];
    }
    __syncthreads();
    uint32_t tmem;
    asm volatile("ld.shared.b32 %0, [%1];" : "=r"(tmem) : "r"(sb + Q_PTR));

    int pc = 0;

#define Q_STAGE_A(TILE)                                                         \
    {                                                                           \
        size_t abase = (size_t)(TILE) * 32768;                                  \
        _Pragma("unroll")                                                       \
        for (int it = 0; it < 8; it++) {                                        \
            uint32_t o = (uint32_t)(t + it * 256) * 16;                         \
            CP_ASYNC16(sb + Q_A + o, Ahi + abase + o);                          \
            CP_ASYNC16(sb + Q_A + 32768 + o, Alo + abase + o);                  \
        }                                                                       \
    }
#define Q_STAGE_B1()                                                            \
    {                                                                           \
        _Pragma("unroll")                                                       \
        for (int it = 0; it < 8; it++) {                                        \
            int idx = t + it * 256;                                             \
            int r = idx >> 3, kg = idx & 7;                                     \
            uint32_t so = SW128((uint32_t)(r * 128 + kg * 16));                 \
            CP_ASYNC16(sb + Q_B1HI + so,         B1hi + (size_t)r * 128 + kg * 8); \
            CP_ASYNC16(sb + Q_B1HI + 32768 + so, B1hi + (size_t)r * 128 + 64 + kg * 8); \
            CP_ASYNC16(sb + Q_B1LO + so,         B1lo + (size_t)r * 128 + kg * 8); \
            CP_ASYNC16(sb + Q_B1LO + 32768 + so, B1lo + (size_t)r * 128 + 64 + kg * 8); \
        }                                                                       \
    }

    for (int tile = blockIdx.x; tile < ntiles; tile += gridDim.x) {
        const int bm = tile * 128;

        // -------- phase 1: y = A @ W1 (48 MMAs, single commit) --------
        Q_STAGE_A(tile);
        Q_STAGE_B1();
        CP_COMMIT();
        CP_WAIT0();
        FENCE_ASYNC();
        __syncthreads();
        if (wid == 0 && elect_one()) {
#pragma unroll
            for (int ch = 0; ch < 2; ch++) {
                uint64_t dA_h = make_desc(sb + Q_A + ch * 16384);
                uint64_t dA_l = make_desc(sb + Q_A + 32768 + ch * 16384);
#pragma unroll
                for (int T = 0; T < 2; T++) {
                    uint64_t bh = make_desc(sb + Q_B1HI + ch * 32768) + T * 1024;
                    uint64_t bl = make_desc(sb + Q_B1LO + ch * 32768) + T * 1024;
                    uint32_t dt = tmem + T * 128;
#pragma unroll
                    for (int s = 0; s < 4; s++)
                        mma_bf16_ss(dt, dA_h + s * 2, bh + s * 2, TG_IDESC,
                                    (ch == 0 && s == 0) ? 0u : 1u);
#pragma unroll
                    for (int s = 0; s < 4; s++)
                        mma_bf16_ss(dt, dA_h + s * 2, bl + s * 2, TG_IDESC, 1u);
#pragma unroll
                    for (int s = 0; s < 4; s++)
                        mma_bf16_ss(dt, dA_l + s * 2, bh + s * 2, TG_IDESC, 1u);
                }
            }
            TC_COMMIT(sb + Q_MBAR);
        }
        MB_WAIT(sb + Q_MBAR, pc & 1); pc++;
        TC_FENCE_AFTER();
        __syncthreads();   // A and B1 regions now dead; safe to reuse

        // -------- phase 2: per 128-col half --------
#pragma unroll
        for (int half = 0; half < 2; half++) {
            if (wid < 4) {
                // produce A2 chunks 2*half, 2*half+1 from y cols [half*128, +128)
                int r = wid * 32 + lid;
#pragma unroll
                for (int p2 = 0; p2 < 2; p2++) {
                    int b0 = half * 4 + p2 * 2;
                    uint32_t r0[32], r1[32];
                    LDTM32(r0, tmem + b0 * 32);
                    LDTM32(r1, tmem + (b0 + 1) * 32);
                    TC_WAIT_LD();
                    float v[64];
#pragma unroll
                    for (int i = 0; i < 32; i++) {
                        int c0 = b0 * 32 + i, c1 = (b0 + 1) * 32 + i;
                        v[i]      = fmaxf(fmaf(__uint_as_float(r0[i]), sSc[c0], sSh[c0]), 0.f);
                        v[32 + i] = fmaxf(fmaf(__uint_as_float(r1[i]), sSc[c1], sSh[c1]), 0.f);
                    }
#pragma unroll
                    for (int bb = 0; bb < 2; bb++) {
                        int blk = b0 + bb;            // absolute 32-col block 0..7
                        int chunk = blk >> 1;         // A2 chunk 0..3
                        const float* vv = v + bb * 32;
#pragma unroll
                        for (int q = 0; q < 4; q++) {
                            uint32_t h[4], lo[4];
#pragma unroll
                            for (int p = 0; p < 4; p++) {
                                float a0 = vv[q * 8 + p * 2], a1 = vv[q * 8 + p * 2 + 1];
                                h[p] = pack_bf16x2(a0, a1);
                                __nv_bfloat162 hb = *reinterpret_cast<__nv_bfloat162*>(&h[p]);
                                float2 hr = __bfloat1622float2(hb);
                                lo[p] = pack_bf16x2(a0 - hr.x, a1 - hr.y);
                            }
                            uint32_t so = SW128((uint32_t)(r * 128 + (blk & 1) * 64 + q * 16));
                            *(uint4*)(smem + Q_B1HI + chunk * 16384 + so) = make_uint4(h[0], h[1], h[2], h[3]);
                            *(uint4*)(smem + Q_B1LO + chunk * 16384 + so) = make_uint4(lo[0], lo[1], lo[2], lo[3]);
                        }
                    }
                }
                TC_FENCE_BEFORE();
            } else {
                // stage B2 chunks 2*half, 2*half+1 into A region buffers
#pragma unroll
                for (int it = 0; it < 8; it++) {
                    int idx = (t - 128) + it * 128;
                    int r = idx >> 3, kg = idx & 7;
                    uint32_t so = SW128((uint32_t)(r * 128 + kg * 16));
                    int c0 = 2 * half, c1 = 2 * half + 1;
                    CP_ASYNC16(sb + Q_A + so,                 B2hi + (size_t)r * 256 + c0 * 64 + kg * 8);
                    CP_ASYNC16(sb + Q_A + 16384 + so,         B2hi + (size_t)r * 256 + c1 * 64 + kg * 8);
                    CP_ASYNC16(sb + Q_A + 32768 + so,         B2lo + (size_t)r * 256 + c0 * 64 + kg * 8);
                    CP_ASYNC16(sb + Q_A + 49152 + so,         B2lo + (size_t)r * 256 + c1 * 64 + kg * 8);
                }
                CP_COMMIT();
                CP_WAIT0();
            }
            FENCE_ASYNC();
            __syncthreads();
            if (wid == 0 && elect_one()) {
#pragma unroll
                for (int cc = 0; cc < 2; cc++) {
                    int c = 2 * half + cc;
                    uint64_t ah = make_desc(sb + Q_B1HI + c * 16384);
                    uint64_t al = make_desc(sb + Q_B1LO + c * 16384);
                    uint64_t bh = make_desc(sb + Q_A + cc * 16384);
                    uint64_t bl = make_desc(sb + Q_A + 32768 + cc * 16384);
#pragma unroll
                    for (int s = 0; s < 4; s++)
                        mma_bf16_ss(tmem, ah + s * 2, bh + s * 2, TG_IDESC,
                                    (c == 0 && s == 0) ? 0u : 1u);
#pragma unroll
                    for (int s = 0; s < 4; s++)
                        mma_bf16_ss(tmem, ah + s * 2, bl + s * 2, TG_IDESC, 1u);
#pragma unroll
                    for (int s = 0; s < 4; s++)
                        mma_bf16_ss(tmem, al + s * 2, bh + s * 2, TG_IDESC, 1u);
                }
                TC_COMMIT(sb + Q_MBAR);
            }
            MB_WAIT(sb + Q_MBAR, pc & 1); pc++;
            TC_FENCE_AFTER();
            __syncthreads();
        }

        // -------- final epilogue: h2 (tmem cols 0..127), 64-row statbuf --------
        for (int pr = 0; pr < 2; pr++) {
#pragma unroll
            for (int rh = 0; rh < 2; rh++) {
                if (wid < 4 && (wid >> 1) == rh) {
                    int rl = (wid & 1) * 32 + lid;
                    int grow = bm + rh * 64 + rl;
                    uint32_t r0[32], r1[32];
                    LDTM32(r0, tmem + pr * 64);
                    LDTM32(r1, tmem + pr * 64 + 32);
                    TC_WAIT_LD();
                    float v0[32], v1[32];
#pragma unroll
                    for (int i = 0; i < 32; i++) {
                        v0[i] = __uint_as_float(r0[i]) + sB[pr * 64 + i];
                        v1[i] = __uint_as_float(r1[i]) + sB[pr * 64 + 32 + i];
                    }
                    if (grow < M) {
                        float* cp = C + (size_t)grow * 128 + pr * 64;
#pragma unroll
                        for (int q = 0; q < 8; q++) {
                            *(float4*)(cp + q * 4)      = *(float4*)(v0 + q * 4);
                            *(float4*)(cp + 32 + q * 4) = *(float4*)(v1 + q * 4);
                        }
                    } else {
#pragma unroll
                        for (int i = 0; i < 32; i++) { v0[i] = 0.f; v1[i] = 0.f; }
                    }
#pragma unroll
                    for (int i = 0; i < 32; i++) {
                        statbuf[rl * 66 + i]      = v0[i];
                        statbuf[rl * 66 + 32 + i] = v1[i];
                    }
                }
                __syncthreads();
                {
                    int c = t & 63, h = t >> 6;
                    float s = 0.f, q = 0.f;
#pragma unroll 8
                    for (int rr = 0; rr < 16; rr++) {
                        float vv = statbuf[(h * 16 + rr) * 66 + c];
                        s += vv;
                        q = fmaf(vv, vv, q);
                    }
                    psum[h * 64 + c] = s;
                    psq[h * 64 + c]  = q;
                }
                __syncthreads();
                if (t < 64) {
                    float s4 = psum[t] + psum[64 + t] + psum[128 + t] + psum[192 + t];
                    float q4 = psq[t]  + psq[64 + t]  + psq[128 + t]  + psq[192 + t];
                    if (rh == 0) { ssl[pr * 64 + t] = s4;  sql[pr * 64 + t] = q4; }
                    else         { ssl[pr * 64 + t] += s4; sql[pr * 64 + t] += q4; }
                }
                __syncthreads();
            }
        }
        if (wid < 4) TC_FENCE_BEFORE();
        __syncthreads();
        if (t < 128) {
            atomicAdd(&g_ssum2[t], ssl[t]);
            atomicAdd(&g_ssq2[t],  sql[t]);
        }
        __syncthreads();
    }
#undef Q_STAGE_A
#undef Q_STAGE_B1

    if (t == 0) MB_INVAL(sb + Q_MBAR);
    if (wid == 0) TC_DEALLOC(tmem, 256);
}

// ---------------- readout pooling (computes outer BN inline) ----------------
__global__ void pool_k(const void* __restrict__ batch, int n,
                       const float* __restrict__ gamma, const float* __restrict__ beta,
                       float invM) {
    long long t = (long long)blockIdx.x * blockDim.x + threadIdx.x;
    long long i = t >> 5;
    if (i >= n) return;
    int lane = (int)(t & 31);
    long long g;
    if (g_i64flag) g = ((const long long*)batch)[i];
    else           g = (long long)((const int*)batch)[i];
    int c = lane * 4;
    float sc[4], sh[4];
#pragma unroll
    for (int j = 0; j < 4; j++) {
        float m   = g_ssum2[c + j] * invM;
        float var = g_ssq2[c + j] * invM - m * m;
        sc[j] = gamma[c + j] * rsqrtf(var + 1e-5f);
        sh[j] = beta[c + j] - m * sc[j];
    }
    float4 v = ((const float4*)g_h2)[i * 32 + lane];
    float r0 = fmaxf(fmaf(v.x, sc[0], sh[0]), 0.f);
    float r1 = fmaxf(fmaf(v.y, sc[1], sh[1]), 0.f);
    float r2 = fmaxf(fmaf(v.z, sc[2], sh[2]), 0.f);
    float r3 = fmaxf(fmaf(v.w, sc[3], sh[3]), 0.f);
    float* ps = g_ps + g * 128 + c;
    asm volatile("red.global.add.v4.f32 [%0], {%1, %2, %3, %4};"
                 :: "l"(ps), "f"(r0), "f"(r1), "f"(r2), "f"(r3) : "memory");
    unsigned int* mx = (unsigned int*)(g_pmx + g * 128 + c);
    atomicMax(mx + 0, __float_as_uint(r0));
    atomicMax(mx + 1, __float_as_uint(r1));
    atomicMax(mx + 2, __float_as_uint(r2));
    atomicMax(mx + 3, __float_as_uint(r3));
    if (lane == 0) atomicAdd(&g_cnt[g], 1.0f);
}

// ---------------- classifier ----------------
__global__ void cgemm1_k(const float* __restrict__ cW1, const float* __restrict__ cb1) {
    int g = blockIdx.x;
    int j = threadIdx.x;
    __shared__ float z[384];
    float cnt = fmaxf(g_cnt[g], 1.0f);
    float sv = g_ps[g * 128 + j];
    z[j]       = sv;
    z[128 + j] = sv / cnt;
    z[256 + j] = g_pmx[g * 128 + j];
    __syncthreads();
    float acc = cb1[j];
#pragma unroll 8
    for (int k = 0; k < 384; k++)
        acc = fmaf(z[k], cW1[k * 128 + j], acc);
    g_z1[g * 128 + j] = acc;
}

__global__ void cstats_k(const float* __restrict__ cg, const float* __restrict__ cbeta) {
    int j = threadIdx.x;
    float s = 0.f, q = 0.f;
    for (int g = 0; g < GCNT; g++) {
        float v = g_z1[g * 128 + j];
        s += v; q += v * v;
    }
    float m   = s * (1.0f / GCNT);
    float var = q * (1.0f / GCNT) - m * m;
    float sc  = cg[j] * rsqrtf(var + 1e-5f);
    g_scale[j] = sc;
    g_shift[j] = cbeta[j] - m * sc;
}

__global__ void chead_k(const float* __restrict__ cW2, const float* __restrict__ cb2,
                        const float* __restrict__ cW3, const float* __restrict__ cb3,
                        float* __restrict__ out) {
    int g = blockIdx.x;
    int j = threadIdx.x;
    __shared__ float a[128];
    __shared__ float z2[64];
    for (int k = j; k < 128; k += 64)
        a[k] = fmaxf(fmaf(g_z1[g * 128 + k], g_scale[k], g_shift[k]), 0.f);
    __syncthreads();
    float acc = cb2[j];
#pragma unroll 8
    for (int k = 0; k < 128; k++)
        acc = fmaf(a[k], cW2[k * 64 + j], acc);
    z2[j] = fmaxf(acc, 0.f);
    __syncthreads();
    if (j < 2) {
        float o = cb3[j];
#pragma unroll 8
        for (int k = 0; k < 64; k++)
            o = fmaf(z2[k], cW3[k * 2 + j], o);
        out[g * 2 + j] = o;
    }
}

// ---------------- launcher ----------------
extern "C" void kernel_launch(void* const* d_in, const int* in_sizes, int n_in,
                              void* d_out, int out_size) {
    const float* x     = (const float*)d_in[0];
    const void*  ei    = d_in[1];
    const void*  batch = d_in[2];
    int base = (in_sizes[3] == 1) ? 4 : 3;
    const float* W1    = (const float*)d_in[base + 0];
    const float* b1    = (const float*)d_in[base + 1];
    const float* g1    = (const float*)d_in[base + 2];
    const float* be1   = (const float*)d_in[base + 3];
    const float* W2    = (const float*)d_in[base + 4];
    const float* b2    = (const float*)d_in[base + 5];
    const float* gbn   = (const float*)d_in[base + 6];
    const float* bbn   = (const float*)d_in[base + 7];
    const float* eps   = (const float*)d_in[base + 8];
    const float* cW1   = (const float*)d_in[base + 9];
    const float* cb1   = (const float*)d_in[base + 10];
    const float* cg    = (const float*)d_in[base + 11];
    const float* cbeta = (const float*)d_in[base + 12];
    const float* cW2   = (const float*)d_in[base + 13];
    const float* cb2   = (const float*)d_in[base + 14];
    const float* cW3   = (const float*)d_in[base + 15];
    const float* cb3   = (const float*)d_in[base + 16];

    int n = in_sizes[0] / 128;
    long long E = (long long)in_sizes[1] / 2;
    int n32 = n * 32;
    int nb = (n32 + 255) / 256;
    int gx = (n + 127) / 128;
    int p1grid = (gx < 148) ? gx : 148;
    int p2grid = (gx < 148) ? gx : 148;
    int eblk = (int)((E + 255) / 256);
    int nscan = (n + 1023) / 1024;
    int ablk = (n * 32 + 255) / 256;
    float invM = 1.0f / (float)n;

    static int smem_set = 0;
    if (!smem_set) {
        cudaFuncSetAttribute(pass1_k, cudaFuncAttributeMaxDynamicSharedMemorySize, P1_SMEM);
        cudaFuncSetAttribute(pass2_k, cudaFuncAttributeMaxDynamicSharedMemorySize, Q_SMEM);
        smem_set = 1;
    }

    float *p_h2;
    uint8_t *p_ahi, *p_alo;
    __nv_bfloat16 *p_b1hi, *p_b1lo, *p_b2hi, *p_b2lo;
    cudaGetSymbolAddress((void**)&p_h2,  g_h2);
    cudaGetSymbolAddress((void**)&p_ahi, g_ahi);
    cudaGetSymbolAddress((void**)&p_alo, g_alo);
    cudaGetSymbolAddress((void**)&p_b1hi, g_b1hi);
    cudaGetSymbolAddress((void**)&p_b1lo, g_b1lo);
    cudaGetSymbolAddress((void**)&p_b2hi, g_b2hi);
    cudaGetSymbolAddress((void**)&p_b2lo, g_b2lo);

    detect_k<<<1, 1>>>((const unsigned int*)ei);
    wconv_k<<<(NLAYER * 256 * 128 + 255) / 256, 256>>>(W1, W2);
    zero_k<<<512, 256>>>(n, gx);

    count_k<<<eblk, 256>>>(ei, E);
    scanA_k<<<nscan, 256>>>(n);
    scanB_k<<<1, 32>>>(nscan);
    scanC_k<<<nscan, 256>>>(n);
    fill_k<<<eblk, 256>>>(ei, E);

    for (int l = 0; l < 4; l++) {
        if (l == 0)
            agg_k<false><<<ablk, 256>>>(x, eps, l, n, nullptr, nullptr, invM);
        else
            agg_k<true><<<ablk, 256>>>(p_h2, eps, l, n,
                                       gbn + (l - 1) * 128, bbn + (l - 1) * 128, invM);

        pass1_k<<<p1grid, 256, P1_SMEM>>>(
            p_ahi, p_alo,
            p_b1hi + (size_t)l * 32768, p_b1lo + (size_t)l * 32768, gx);
        pass2_k<<<p2grid, 256, Q_SMEM>>>(
            p_ahi, p_alo,
            p_b1hi + (size_t)l * 32768, p_b1lo + (size_t)l * 32768,
            p_b2hi + (size_t)l * 32768, p_b2lo + (size_t)l * 32768,
            b1 + l * 256, b2 + l * 128, g1 + l * 256, be1 + l * 256, invM,
            p_h2, n, gx);
    }

    pool_k<<<nb, 256>>>(batch, n, gbn + 3 * 128, bbn + 3 * 128, invM);
    cgemm1_k<<<GCNT, 128>>>(cW1, cb1);
    cstats_k<<<1, 128>>>(cg, cbeta);
    chead_k<<<GCNT, 64>>>(cW2, cb2, cW3, cb3, (float*)d_out);
}

// round 17
// speedup vs baseline: 1.1028x; 1.0410x over previous
#include <cuda_runtime.h>
#include <cuda_bf16.h>
#include <cstdint>
#include <cstddef>

// Problem constants (fixed shapes)
#define NMAX 100000
#define EMAX 500000
#define GCNT 512
#define NLAYER 4
#define NTILE ((NMAX + 127) / 128)   // 782

// tcgen05 only exists in the arch-specific (sm_103a) device pass.
#if defined(__CUDA_ARCH__) && defined(__CUDA_ARCH_FEAT_SM103_ALL)
#define HAS_TC 1
#else
#define HAS_TC 0
#endif

// ---------------- device scratch ----------------
__device__ float g_h2 [NMAX * 128];
// aggregated layer input, pre-split bf16 hi/lo, pre-swizzled smem image:
// [tile][chunk(2)][16KB image]  where image[SW128(row*128 + kg*16)]
__device__ uint8_t g_ahi[(size_t)NTILE * 32768];
__device__ uint8_t g_alo[(size_t)NTILE * 32768];
__device__ float g_ssum [256];
__device__ float g_ssq  [256];
__device__ float g_ssum2[128];
__device__ float g_ssq2 [128];
__device__ float g_scale[256];   // used by classifier only now
__device__ float g_shift[256];
__device__ float g_ps [GCNT * 128];
__device__ float g_pmx[GCNT * 128];
__device__ float g_cnt[GCNT];
__device__ float g_z1 [GCNT * 128];
__device__ int   g_i64flag;

// CSR (built once per launch; edges fixed across layers)
__device__ int g_deg [NMAX];
__device__ int g_off [NMAX];
__device__ int g_cur [NMAX];
__device__ int g_csr [EMAX];
__device__ int g_bsum[128];
__device__ int g_bscn[128];

// pre-split weights, B layout: [layer][n(out)][k(in)] bf16, K-major rows
__device__ __nv_bfloat16 g_b1hi[NLAYER * 256 * 128];
__device__ __nv_bfloat16 g_b1lo[NLAYER * 256 * 128];
__device__ __nv_bfloat16 g_b2hi[NLAYER * 128 * 256];
__device__ __nv_bfloat16 g_b2lo[NLAYER * 128 * 256];

// ---------------- PTX helpers ----------------
__device__ __forceinline__ uint32_t smem_u32(const void* p) {
    uint32_t a;
    asm("{ .reg .u64 t; cvta.to.shared.u64 t, %1; cvt.u32.u64 %0, t; }" : "=r"(a) : "l"(p));
    return a;
}
__device__ __forceinline__ uint32_t elect_one() {
    uint32_t p;
    asm volatile("{ .reg .pred p; elect.sync _|p, 0xFFFFFFFF; selp.b32 %0, 1, 0, p; }" : "=r"(p));
    return p;
}
#define SW128(o) ((o) ^ (((o) >> 3) & 0x70))
static __device__ __forceinline__ uint64_t make_desc(uint32_t addr) {
    return ((uint64_t)2 << 61) | ((uint64_t)1 << 46) | ((uint64_t)64 << 32) |
           ((uint64_t)1 << 16) | ((uint64_t)(addr >> 4) & 0x3FFF);
}

#if HAS_TC
__device__ __forceinline__ void mma_bf16_ss(uint32_t d, uint64_t a, uint64_t b,
                                            uint32_t idesc, uint32_t en) {
    asm volatile(
        "{\n\t.reg .pred p;\n\tsetp.ne.u32 p, %4, 0;\n\t"
        "tcgen05.mma.cta_group::1.kind::f16 [%0], %1, %2, %3, {%5, %5, %5, %5}, p;\n\t}"
        :: "r"(d), "l"(a), "l"(b), "r"(idesc), "r"(en), "r"(0u) : "memory");
}
__device__ __forceinline__ void mma_bf16_ts(uint32_t d, uint32_t a, uint64_t b,
                                            uint32_t idesc, uint32_t en) {
    asm volatile(
        "{\n\t.reg .pred p;\n\tsetp.ne.u32 p, %4, 0;\n\t"
        "tcgen05.mma.cta_group::1.kind::f16 [%0], [%1], %2, %3, {%5, %5, %5, %5}, p;\n\t}"
        :: "r"(d), "r"(a), "l"(b), "r"(idesc), "r"(en), "r"(0u) : "memory");
}
#define TC_ALLOC(sm, n)  asm volatile("tcgen05.alloc.cta_group::1.sync.aligned.shared::cta.b32 [%0], %1;" :: "r"(sm), "r"((uint32_t)(n)) : "memory")
#define TC_DEALLOC(t, n) asm volatile("tcgen05.dealloc.cta_group::1.sync.aligned.b32 %0, %1;" :: "r"(t), "r"((uint32_t)(n)))
#define TC_COMMIT(mb)    asm volatile("tcgen05.commit.cta_group::1.mbarrier::arrive::one.shared::cluster.b64 [%0];" :: "r"(mb) : "memory")
#define TC_FENCE_AFTER() asm volatile("tcgen05.fence::after_thread_sync;" ::: "memory")
#define TC_FENCE_BEFORE() asm volatile("tcgen05.fence::before_thread_sync;" ::: "memory")
#define TC_WAIT_LD()     asm volatile("tcgen05.wait::ld.sync.aligned;" ::: "memory")
#define TC_WAIT_ST()     asm volatile("tcgen05.wait::st.sync.aligned;" ::: "memory")
#define LDTM32(r, a)                                                            \
    asm volatile("tcgen05.ld.sync.aligned.32x32b.x32.b32 "                      \
        "{%0,%1,%2,%3,%4,%5,%6,%7,%8,%9,%10,%11,%12,%13,%14,%15,"               \
        "%16,%17,%18,%19,%20,%21,%22,%23,%24,%25,%26,%27,%28,%29,%30,%31}, [%32];" \
        : "=r"((r)[0]),"=r"((r)[1]),"=r"((r)[2]),"=r"((r)[3]),                  \
          "=r"((r)[4]),"=r"((r)[5]),"=r"((r)[6]),"=r"((r)[7]),                  \
          "=r"((r)[8]),"=r"((r)[9]),"=r"((r)[10]),"=r"((r)[11]),                \
          "=r"((r)[12]),"=r"((r)[13]),"=r"((r)[14]),"=r"((r)[15]),              \
          "=r"((r)[16]),"=r"((r)[17]),"=r"((r)[18]),"=r"((r)[19]),              \
          "=r"((r)[20]),"=r"((r)[21]),"=r"((r)[22]),"=r"((r)[23]),              \
          "=r"((r)[24]),"=r"((r)[25]),"=r"((r)[26]),"=r"((r)[27]),              \
          "=r"((r)[28]),"=r"((r)[29]),"=r"((r)[30]),"=r"((r)[31])               \
        : "r"(a))
#define STTM32(a, r)                                                            \
    asm volatile("tcgen05.st.sync.aligned.32x32b.x32.b32 [%0], "                \
        "{%1,%2,%3,%4,%5,%6,%7,%8,%9,%10,%11,%12,%13,%14,%15,%16,"              \
        "%17,%18,%19,%20,%21,%22,%23,%24,%25,%26,%27,%28,%29,%30,%31,%32};"     \
        :: "r"(a),                                                              \
           "r"((r)[0]),"r"((r)[1]),"r"((r)[2]),"r"((r)[3]),                     \
           "r"((r)[4]),"r"((r)[5]),"r"((r)[6]),"r"((r)[7]),                     \
           "r"((r)[8]),"r"((r)[9]),"r"((r)[10]),"r"((r)[11]),                   \
           "r"((r)[12]),"r"((r)[13]),"r"((r)[14]),"r"((r)[15]),                 \
           "r"((r)[16]),"r"((r)[17]),"r"((r)[18]),"r"((r)[19]),                 \
           "r"((r)[20]),"r"((r)[21]),"r"((r)[22]),"r"((r)[23]),                 \
           "r"((r)[24]),"r"((r)[25]),"r"((r)[26]),"r"((r)[27]),                 \
           "r"((r)[28]),"r"((r)[29]),"r"((r)[30]),"r"((r)[31])                  \
        : "memory")
#define MB_WAIT(mb, par) do {                                                   \
    uint32_t _m = (mb), _p = (par), _d;                                         \
    asm volatile("{ .reg .pred p; mbarrier.try_wait.parity.acquire.cta.shared::cta.b64 p, [%1], %2; selp.b32 %0, 1, 0, p; }" \
                 : "=r"(_d) : "r"(_m), "r"(_p) : "memory");                     \
    if (!_d) {                                                                  \
        asm volatile("{ .reg .pred P1; W%=: mbarrier.try_wait.parity.acquire.cta.shared::cta.b64 P1, [%0], %1, 0x989680; @P1 bra.uni D%=; bra.uni W%=; D%=: }" \
                     :: "r"(_m), "r"(_p) : "memory");                           \
    }                                                                           \
} while (0)
#else
__device__ __forceinline__ void mma_bf16_ss(uint32_t, uint64_t, uint64_t, uint32_t, uint32_t) {}
__device__ __forceinline__ void mma_bf16_ts(uint32_t, uint32_t, uint64_t, uint32_t, uint32_t) {}
#define TC_ALLOC(sm, n)   ((void)0)
#define TC_DEALLOC(t, n)  ((void)0)
#define TC_COMMIT(mb)     ((void)0)
#define TC_FENCE_AFTER()  ((void)0)
#define TC_FENCE_BEFORE() ((void)0)
#define TC_WAIT_LD()      ((void)0)
#define TC_WAIT_ST()      ((void)0)
#define LDTM32(r, a)      do { _Pragma("unroll") for (int _i = 0; _i < 32; _i++) (r)[_i] = 0u; } while (0)
#define STTM32(a, r)      ((void)0)
#define MB_WAIT(mb, par)  ((void)0)
#endif

#define MB_INIT(mb, c)   asm volatile("mbarrier.init.shared.b64 [%0], %1;" :: "r"(mb), "r"((uint32_t)(c)) : "memory")
#define MB_INVAL(mb)     asm volatile("mbarrier.inval.shared.b64 [%0];" :: "r"(mb) : "memory")
#define FENCE_ASYNC()    asm volatile("fence.proxy.async.shared::cta;" ::: "memory")
#define CP_ASYNC16(dst, src) asm volatile("cp.async.ca.shared.global [%0], [%1], 16;" :: "r"(dst), "l"(src) : "memory")
#define CP_COMMIT()      asm volatile("cp.async.commit_group;" ::: "memory")
#define CP_WAIT0()       asm volatile("cp.async.wait_group 0;" ::: "memory")

// ---------------- dtype detection ----------------
__global__ void detect_k(const unsigned int* __restrict__ e) {
    unsigned acc = 0;
    for (int i = 1; i < 128; i += 2) acc |= e[i];
    g_i64flag = (acc == 0u) ? 1 : 0;
}

// ---------------- weight split fp32 -> bf16 hi/lo ----------------
__global__ void wconv_k(const float* __restrict__ W1, const float* __restrict__ W2) {
    int i = blockIdx.x * 256 + threadIdx.x;
    const int tot = NLAYER * 256 * 128;
    if (i >= tot) return;
    int l = i / (256 * 128), rem = i % (256 * 128);
    {
        int n = rem / 128, k = rem % 128;
        float w = W1[l * 32768 + k * 256 + n];
        __nv_bfloat16 h = __float2bfloat16(w);
        g_b1hi[i] = h;
        g_b1lo[i] = __float2bfloat16(w - __bfloat162float(h));
    }
    {
        int n = rem / 256, k = rem % 256;
        float w = W2[l * 32768 + k * 128 + n];
        __nv_bfloat16 h = __float2bfloat16(w);
        g_b2hi[i] = h;
        g_b2lo[i] = __float2bfloat16(w - __bfloat162float(h));
    }
}

// ---------------- zero (grid-stride; covers n + pad tile image) ----------------
__global__ void zero_k(int n, int gx) {
    int tot = (n > GCNT * 128) ? n : GCNT * 128;
    for (int i = blockIdx.x * blockDim.x + threadIdx.x; i < tot;
         i += gridDim.x * blockDim.x) {
        if (i < 256) { g_ssum[i] = 0.f; g_ssq[i] = 0.f; }
        if (i < 128) { g_ssum2[i] = 0.f; g_ssq2[i] = 0.f; }
        if (i < GCNT * 128) { g_ps[i] = 0.f; g_pmx[i] = 0.f; }
        if (i < GCNT) g_cnt[i] = 0.f;
        if (i < n) g_deg[i] = 0;
    }
    size_t lt = (size_t)(gx - 1) * 32768;
    for (int i = blockIdx.x * blockDim.x + threadIdx.x; i < 32768 / 16;
         i += gridDim.x * blockDim.x) {
        ((uint4*)(g_ahi + lt))[i] = make_uint4(0, 0, 0, 0);
        ((uint4*)(g_alo + lt))[i] = make_uint4(0, 0, 0, 0);
    }
}

// ---------------- CSR build ----------------
__global__ void count_k(const void* __restrict__ ei, long long E) {
    long long e = (long long)blockIdx.x * blockDim.x + threadIdx.x;
    if (e >= E) return;
    int d;
    if (g_i64flag) d = (int)((const long long*)ei)[E + e];
    else           d = ((const int*)ei)[E + e];
    atomicAdd(&g_deg[d], 1);
}

__global__ void scanA_k(int n) {
    __shared__ int sred[256];
    int blk = blockIdx.x, t = threadIdx.x;
    int base = blk * 1024 + t * 4;
    int s = 0;
#pragma unroll
    for (int j = 0; j < 4; j++) {
        int idx = base + j;
        if (idx < n) s += g_deg[idx];
    }
    sred[t] = s;
    __syncthreads();
    for (int o = 128; o > 0; o >>= 1) {
        if (t < o) sred[t] += sred[t + o];
        __syncthreads();
    }
    if (t == 0) g_bsum[blk] = sred[0];
}

__global__ void scanB_k(int nblk) {
    if (threadIdx.x == 0) {
        int run = 0;
        for (int i = 0; i < nblk; i++) { g_bscn[i] = run; run += g_bsum[i]; }
    }
}

__global__ void scanC_k(int n) {
    __shared__ int sth[256];
    int blk = blockIdx.x, t = threadIdx.x;
    int base = blk * 1024 + t * 4;
    int v[4];
    int s = 0;
#pragma unroll
    for (int j = 0; j < 4; j++) {
        int idx = base + j;
        v[j] = (idx < n) ? g_deg[idx] : 0;
        s += v[j];
    }
    sth[t] = s;
    __syncthreads();
    for (int o = 1; o < 256; o <<= 1) {
        int add = (t >= o) ? sth[t - o] : 0;
        __syncthreads();
        sth[t] += add;
        __syncthreads();
    }
    int tpre = (t > 0 ? sth[t - 1] : 0) + g_bscn[blk];
#pragma unroll
    for (int j = 0; j < 4; j++) {
        int idx = base + j;
        if (idx < n) { g_off[idx] = tpre; g_cur[idx] = tpre; }
        tpre += v[j];
    }
}

__global__ void fill_k(const void* __restrict__ ei, long long E) {
    long long e = (long long)blockIdx.x * blockDim.x + threadIdx.x;
    if (e >= E) return;
    int s, d;
    if (g_i64flag) {
        const long long* p = (const long long*)ei;
        s = (int)p[e]; d = (int)p[E + e];
    } else {
        const int* p = (const int*)ei;
        s = p[e]; d = p[E + e];
    }
    int pos = atomicAdd(&g_cur[d], 1);
    if (pos < EMAX) g_csr[pos] = s;
}

__device__ __forceinline__ uint32_t pack_bf16x2(float a, float b) {
    __nv_bfloat162 h = __float22bfloat162_rn(make_float2(a, b));
    return *reinterpret_cast<uint32_t*>(&h);
}

// ---------------- CSR aggregation + bf16 split + swizzled store ----------------
template<bool BN>
__global__ void __launch_bounds__(256) agg_k(
    const float* __restrict__ SRC, const float* __restrict__ epsp, int l, int n,
    const float* __restrict__ gamma, const float* __restrict__ beta, float invM) {
    if (BN && blockIdx.x == 0) {
        g_ssum[threadIdx.x] = 0.f;
        g_ssq[threadIdx.x]  = 0.f;
    }
    int node = (int)(((long long)blockIdx.x * blockDim.x + threadIdx.x) >> 5);
    int lane = threadIdx.x & 31;
    if (node >= n) return;
    float e = 1.0f + epsp[l];

    float sc0, sc1, sc2, sc3, sh0, sh1, sh2, sh3;
    if (BN) {
        int c = lane * 4;
#pragma unroll
        for (int j = 0; j < 4; j++) {
            float m   = g_ssum2[c + j] * invM;
            float var = g_ssq2[c + j] * invM - m * m;
            float sc  = gamma[c + j] * rsqrtf(var + 1e-5f);
            float sh  = beta[c + j] - m * sc;
            if (j == 0) { sc0 = sc; sh0 = sh; }
            else if (j == 1) { sc1 = sc; sh1 = sh; }
            else if (j == 2) { sc2 = sc; sh2 = sh; }
            else { sc3 = sc; sh3 = sh; }
        }
    }
#define FBN(v)                                                                   \
    if (BN) {                                                                    \
        v.x = fmaxf(fmaf(v.x, sc0, sh0), 0.f);                                   \
        v.y = fmaxf(fmaf(v.y, sc1, sh1), 0.f);                                   \
        v.z = fmaxf(fmaf(v.z, sc2, sh2), 0.f);                                   \
        v.w = fmaxf(fmaf(v.w, sc3, sh3), 0.f);                                   \
    }

    int beg = g_off[node];
    int deg = g_deg[node];

    float4 self = ((const float4*)SRC)[(size_t)node * 32 + lane];
    FBN(self);
    float4 a0 = make_float4(self.x * e, self.y * e, self.z * e, self.w * e);
    float4 a1 = make_float4(0.f, 0.f, 0.f, 0.f);
    float4 a2 = make_float4(0.f, 0.f, 0.f, 0.f);
    float4 a3 = make_float4(0.f, 0.f, 0.f, 0.f);

    int i = 0;
    for (; i + 4 <= deg; i += 4) {
        int s0 = g_csr[beg + i];
        int s1 = g_csr[beg + i + 1];
        int s2 = g_csr[beg + i + 2];
        int s3 = g_csr[beg + i + 3];
        float4 v0 = ((const float4*)SRC)[(size_t)s0 * 32 + lane];
        float4 v1 = ((const float4*)SRC)[(size_t)s1 * 32 + lane];
        float4 v2 = ((const float4*)SRC)[(size_t)s2 * 32 + lane];
        float4 v3 = ((const float4*)SRC)[(size_t)s3 * 32 + lane];
        FBN(v0); FBN(v1); FBN(v2); FBN(v3);
        a0.x += v0.x; a0.y += v0.y; a0.z += v0.z; a0.w += v0.w;
        a1.x += v1.x; a1.y += v1.y; a1.z += v1.z; a1.w += v1.w;
        a2.x += v2.x; a2.y += v2.y; a2.z += v2.z; a2.w += v2.w;
        a3.x += v3.x; a3.y += v3.y; a3.z += v3.z; a3.w += v3.w;
    }
    if (i < deg) {
        int rem = deg - i;
        int s0 = g_csr[beg + i];
        int s1 = g_csr[beg + ((rem > 1) ? i + 1 : i)];
        int s2 = g_csr[beg + ((rem > 2) ? i + 2 : i)];
        float4 v0 = ((const float4*)SRC)[(size_t)s0 * 32 + lane];
        float4 v1 = ((const float4*)SRC)[(size_t)s1 * 32 + lane];
        float4 v2 = ((const float4*)SRC)[(size_t)s2 * 32 + lane];
        FBN(v0); FBN(v1); FBN(v2);
        a1.x += v0.x; a1.y += v0.y; a1.z += v0.z; a1.w += v0.w;
        if (rem > 1) { a2.x += v1.x; a2.y += v1.y; a2.z += v1.z; a2.w += v1.w; }
        if (rem > 2) { a3.x += v2.x; a3.y += v2.y; a3.z += v2.z; a3.w += v2.w; }
    }
#undef FBN
    float4 r;
    r.x = (a0.x + a1.x) + (a2.x + a3.x);
    r.y = (a0.y + a1.y) + (a2.y + a3.y);
    r.z = (a0.z + a1.z) + (a2.z + a3.z);
    r.w = (a0.w + a1.w) + (a2.w + a3.w);

    uint32_t h0 = pack_bf16x2(r.x, r.y);
    uint32_t h1 = pack_bf16x2(r.z, r.w);
    __nv_bfloat162 hb0 = *reinterpret_cast<__nv_bfloat162*>(&h0);
    __nv_bfloat162 hb1 = *reinterpret_cast<__nv_bfloat162*>(&h1);
    float2 hr0 = __bfloat1622float2(hb0);
    float2 hr1 = __bfloat1622float2(hb1);
    uint32_t l0 = pack_bf16x2(r.x - hr0.x, r.y - hr0.y);
    uint32_t l1 = pack_bf16x2(r.z - hr1.x, r.w - hr1.y);

    int T = node >> 7, rr = node & 127;
    int c8 = lane >> 4;
    int g8 = (lane >> 1) & 7;
    int half = lane & 1;
    size_t base = ((size_t)T * 2 + c8) * 16384
                + SW128((uint32_t)(rr * 128 + g8 * 16)) + half * 8;
    *(uint2*)(g_ahi + base) = make_uint2(h0, h1);
    *(uint2*)(g_alo + base) = make_uint2(l0, l1);
}

#define TG_IDESC 0x8200490u

// ================== PASS 1: occ-1, B1 fully resident (R15 form) ==================
#define P1_PTR   0
#define P1_MBAR  16
#define P1_PSUM  32
#define P1_PSQ   1056
#define P1_SSL   2080
#define P1_SQL   3104
#define P1_STAT  4128
#define P1_AHI   21504
#define P1_ALO   54272
#define P1_B1HI  87040
#define P1_B1LO  152576
#define P1_SMEM  218112

__global__ void __launch_bounds__(256, 1) pass1_k(
    const uint8_t* __restrict__ Ahi, const uint8_t* __restrict__ Alo,
    const __nv_bfloat16* __restrict__ B1hi, const __nv_bfloat16* __restrict__ B1lo,
    int ntiles)
{
    extern __shared__ char smem[];
    const uint32_t sb = smem_u32(smem);
    const int t = threadIdx.x, wid = t >> 5, lid = t & 31;
    float* psum = reinterpret_cast<float*>(smem + P1_PSUM);
    float* psq  = reinterpret_cast<float*>(smem + P1_PSQ);
    float* ssl  = reinterpret_cast<float*>(smem + P1_SSL);
    float* sql  = reinterpret_cast<float*>(smem + P1_SQL);
    float* statbuf = reinterpret_cast<float*>(smem + P1_STAT);

    if (blockIdx.x == 0 && t < 128) {
        g_ssum2[t] = 0.f;
        g_ssq2[t]  = 0.f;
    }
    if (wid == 0) TC_ALLOC(sb + P1_PTR, 256);
    if (t == 0) MB_INIT(sb + P1_MBAR, 1);
    __syncthreads();
    uint32_t tmem;
    asm volatile("ld.shared.b32 %0, [%1];" : "=r"(tmem) : "r"(sb + P1_PTR));

#pragma unroll
    for (int it = 0; it < 8; it++) {
        int idx = t + it * 256;
        int r = idx >> 3, kg = idx & 7;
        uint32_t so = SW128((uint32_t)(r * 128 + kg * 16));
        CP_ASYNC16(sb + P1_B1HI + so,         B1hi + (size_t)r * 128 + kg * 8);
        CP_ASYNC16(sb + P1_B1HI + 32768 + so, B1hi + (size_t)r * 128 + 64 + kg * 8);
        CP_ASYNC16(sb + P1_B1LO + so,         B1lo + (size_t)r * 128 + kg * 8);
        CP_ASYNC16(sb + P1_B1LO + 32768 + so, B1lo + (size_t)r * 128 + 64 + kg * 8);
    }

#define P1_STAGE_A(TILE)                                                        \
    {                                                                           \
        size_t abase = (size_t)(TILE) * 32768;                                  \
        _Pragma("unroll")                                                       \
        for (int it = 0; it < 8; it++) {                                        \
            uint32_t o = (uint32_t)(t + it * 256) * 16;                         \
            CP_ASYNC16(sb + P1_AHI + o, Ahi + abase + o);                       \
            CP_ASYNC16(sb + P1_ALO + o, Alo + abase + o);                       \
        }                                                                       \
    }

    if (blockIdx.x < ntiles) P1_STAGE_A(blockIdx.x);
    CP_COMMIT();

    int pc = 0;
    for (int tile = blockIdx.x; tile < ntiles; tile += gridDim.x) {
        CP_WAIT0();
        FENCE_ASYNC();
        __syncthreads();
        if (wid == 0 && elect_one()) {
#pragma unroll
            for (int ch = 0; ch < 2; ch++) {
                uint64_t dA_h = make_desc(sb + P1_AHI + ch * 16384);
                uint64_t dA_l = make_desc(sb + P1_ALO + ch * 16384);
#pragma unroll
                for (int T = 0; T < 2; T++) {
                    uint64_t bh = make_desc(sb + P1_B1HI + ch * 32768) + T * 1024;
                    uint64_t bl = make_desc(sb + P1_B1LO + ch * 32768) + T * 1024;
                    uint32_t dt = tmem + T * 128;
#pragma unroll
                    for (int s = 0; s < 4; s++)
                        mma_bf16_ss(dt, dA_h + s * 2, bh + s * 2, TG_IDESC,
                                    (ch == 0 && s == 0) ? 0u : 1u);
#pragma unroll
                    for (int s = 0; s < 4; s++)
                        mma_bf16_ss(dt, dA_h + s * 2, bl + s * 2, TG_IDESC, 1u);
#pragma unroll
                    for (int s = 0; s < 4; s++)
                        mma_bf16_ss(dt, dA_l + s * 2, bh + s * 2, TG_IDESC, 1u);
                }
            }
            TC_COMMIT(sb + P1_MBAR);
        }
        MB_WAIT(sb + P1_MBAR, pc & 1); pc++;
        TC_FENCE_AFTER();

        int nxt = tile + gridDim.x;
        if (nxt < ntiles) {
            __syncthreads();
            P1_STAGE_A(nxt);
            CP_COMMIT();
        }

        for (int pr = 0; pr < 4; pr++) {
#pragma unroll
            for (int rh = 0; rh < 2; rh++) {
                if (wid < 4 && (wid >> 1) == rh) {
                    uint32_t r0[32], r1[32];
                    LDTM32(r0, tmem + pr * 64);
                    LDTM32(r1, tmem + pr * 64 + 32);
                    TC_WAIT_LD();
                    int rl = (wid & 1) * 32 + lid;
#pragma unroll
                    for (int i = 0; i < 32; i++) {
                        statbuf[rl * 66 + i]      = __uint_as_float(r0[i]);
                        statbuf[rl * 66 + 32 + i] = __uint_as_float(r1[i]);
                    }
                }
                __syncthreads();
                {
                    int c = t & 63, h = t >> 6;
                    float s = 0.f, q = 0.f;
#pragma unroll 8
                    for (int rr = 0; rr < 16; rr++) {
                        float v = statbuf[(h * 16 + rr) * 66 + c];
                        s += v;
                        q = fmaf(v, v, q);
                    }
                    psum[h * 64 + c] = s;
                    psq[h * 64 + c]  = q;
                }
                __syncthreads();
                if (t < 64) {
                    float s4 = psum[t] + psum[64 + t] + psum[128 + t] + psum[192 + t];
                    float q4 = psq[t]  + psq[64 + t]  + psq[128 + t]  + psq[192 + t];
                    if (rh == 0) { ssl[pr * 64 + t] = s4;  sql[pr * 64 + t] = q4; }
                    else         { ssl[pr * 64 + t] += s4; sql[pr * 64 + t] += q4; }
                }
                __syncthreads();
            }
        }
        if (wid < 4) TC_FENCE_BEFORE();
        __syncthreads();
        atomicAdd(&g_ssum[t], ssl[t]);
        atomicAdd(&g_ssq[t],  sql[t]);
        __syncthreads();
    }
#undef P1_STAGE_A

    CP_WAIT0();
    if (t == 0) MB_INVAL(sb + P1_MBAR);
    if (wid == 0) TC_DEALLOC(tmem, 256);
}

// ================== PASS 2: occ-1, B1 resident, A2 in TMEM (TS mode) ==================
// TMEM: y/h2 cols 0..255, A2hi cols 256..383, A2lo cols 384..511.
// phase1: A tile + resident B1 -> 48 SS MMAs single commit -> y (cols 0..255).
// phase2 per half: warps 0-3 LDTM y, bnrelu, split, STTM A2; warps 4-7 cp.async B2
//   chunks into dead A region; 24 TS MMAs single commit -> h2 accum (cols 0..127).
#define Q_PTR   0
#define Q_MBAR  16
#define Q_SC    32
#define Q_SH    1056
#define Q_SB    2080
#define Q_SSL   2592
#define Q_SQL   3104
#define Q_PSUM  3616
#define Q_PSQ   4640
#define Q_A     8192     // phase1 A: hi ch0/ch1 @+0/+16384, lo @+32768/+49152
                         // phase2 B2: hi buf0/buf1 @+0/+16384, lo @+32768/+49152
#define Q_B1HI  73728    // resident: ch0@+0, ch1@+32768
#define Q_B1LO  139264   // resident: ch0@+0, ch1@+32768
#define Q_STAT  204800   // 64*66 f -> end 221696
#define Q_SMEM  221696
#define TM_A2HI 256
#define TM_A2LO 384

__global__ void __launch_bounds__(256, 1) pass2_k(
    const uint8_t* __restrict__ Ahi, const uint8_t* __restrict__ Alo,
    const __nv_bfloat16* __restrict__ B1hi, const __nv_bfloat16* __restrict__ B1lo,
    const __nv_bfloat16* __restrict__ B2hi, const __nv_bfloat16* __restrict__ B2lo,
    const float* __restrict__ b1, const float* __restrict__ b2,
    const float* __restrict__ g1, const float* __restrict__ be1, float invM,
    float* __restrict__ C, int M, int ntiles)
{
    extern __shared__ char smem[];
    const uint32_t sb = smem_u32(smem);
    const int t = threadIdx.x, wid = t >> 5, lid = t & 31;
    float* sSc = reinterpret_cast<float*>(smem + Q_SC);
    float* sSh = reinterpret_cast<float*>(smem + Q_SH);
    float* sB  = reinterpret_cast<float*>(smem + Q_SB);
    float* ssl = reinterpret_cast<float*>(smem + Q_SSL);
    float* sql = reinterpret_cast<float*>(smem + Q_SQL);
    float* psum = reinterpret_cast<float*>(smem + Q_PSUM);
    float* psq  = reinterpret_cast<float*>(smem + Q_PSQ);
    float* statbuf = reinterpret_cast<float*>(smem + Q_STAT);

    if (wid == 0) TC_ALLOC(sb + Q_PTR, 512);
    if (t == 0) MB_INIT(sb + Q_MBAR, 1);
    {
        float mraw = g_ssum[t] * invM;
        float var  = g_ssq[t] * invM - mraw * mraw;
        float sc   = g1[t] * rsqrtf(var + 1e-5f);
        sSc[t] = sc;
        sSh[t] = fmaf(-mraw, sc, be1[t]);
        if (t < 128) sB[t] = b2[t];
    }
    __syncthreads();
    uint32_t tmem;
    asm volatile("ld.shared.b32 %0, [%1];" : "=r"(tmem) : "r"(sb + Q_PTR));

    // stage B1 resident (once)
#pragma unroll
    for (int it = 0; it < 8; it++) {
        int idx = t + it * 256;
        int r = idx >> 3, kg = idx & 7;
        uint32_t so = SW128((uint32_t)(r * 128 + kg * 16));
        CP_ASYNC16(sb + Q_B1HI + so,         B1hi + (size_t)r * 128 + kg * 8);
        CP_ASYNC16(sb + Q_B1HI + 32768 + so, B1hi + (size_t)r * 128 + 64 + kg * 8);
        CP_ASYNC16(sb + Q_B1LO + so,         B1lo + (size_t)r * 128 + kg * 8);
        CP_ASYNC16(sb + Q_B1LO + 32768 + so, B1lo + (size_t)r * 128 + 64 + kg * 8);
    }

    int pc = 0;

#define Q_STAGE_A(TILE)                                                         \
    {                                                                           \
        size_t abase = (size_t)(TILE) * 32768;                                  \
        _Pragma("unroll")                                                       \
        for (int it = 0; it < 8; it++) {                                        \
            uint32_t o = (uint32_t)(t + it * 256) * 16;                         \
            CP_ASYNC16(sb + Q_A + o, Ahi + abase + o);                          \
            CP_ASYNC16(sb + Q_A + 32768 + o, Alo + abase + o);                  \
        }                                                                       \
    }

    for (int tile = blockIdx.x; tile < ntiles; tile += gridDim.x) {
        const int bm = tile * 128;

        // -------- phase 1: y = A @ W1 (48 SS MMAs, single commit) --------
        Q_STAGE_A(tile);
        CP_COMMIT();
        CP_WAIT0();
        FENCE_ASYNC();
        __syncthreads();
        if (wid == 0 && elect_one()) {
#pragma unroll
            for (int ch = 0; ch < 2; ch++) {
                uint64_t dA_h = make_desc(sb + Q_A + ch * 16384);
                uint64_t dA_l = make_desc(sb + Q_A + 32768 + ch * 16384);
#pragma unroll
                for (int T = 0; T < 2; T++) {
                    uint64_t bh = make_desc(sb + Q_B1HI + ch * 32768) + T * 1024;
                    uint64_t bl = make_desc(sb + Q_B1LO + ch * 32768) + T * 1024;
                    uint32_t dt = tmem + T * 128;
#pragma unroll
                    for (int s = 0; s < 4; s++)
                        mma_bf16_ss(dt, dA_h + s * 2, bh + s * 2, TG_IDESC,
                                    (ch == 0 && s == 0) ? 0u : 1u);
#pragma unroll
                    for (int s = 0; s < 4; s++)
                        mma_bf16_ss(dt, dA_h + s * 2, bl + s * 2, TG_IDESC, 1u);
#pragma unroll
                    for (int s = 0; s < 4; s++)
                        mma_bf16_ss(dt, dA_l + s * 2, bh + s * 2, TG_IDESC, 1u);
                }
            }
            TC_COMMIT(sb + Q_MBAR);
        }
        MB_WAIT(sb + Q_MBAR, pc & 1); pc++;
        TC_FENCE_AFTER();
        __syncthreads();   // A region now dead; safe to reuse for B2

        // -------- phase 2: per 128-col half --------
#pragma unroll
        for (int half = 0; half < 2; half++) {
            if (wid < 4) {
                // convert y cols [half*128, +128) -> A2 TMEM cols [half*64, +64)
                uint32_t woff = ((uint32_t)wid) << 21;   // explicit lane-group offset for st
#pragma unroll
                for (int p2 = 0; p2 < 2; p2++) {
                    int b0 = half * 4 + p2 * 2;
                    uint32_t r0[32], r1[32];
                    LDTM32(r0, tmem + b0 * 32);
                    LDTM32(r1, tmem + (b0 + 1) * 32);
                    TC_WAIT_LD();
                    float v[64];
#pragma unroll
                    for (int i = 0; i < 32; i++) {
                        int c0 = b0 * 32 + i, c1 = (b0 + 1) * 32 + i;
                        v[i]      = fmaxf(fmaf(__uint_as_float(r0[i]), sSc[c0], sSh[c0]), 0.f);
                        v[32 + i] = fmaxf(fmaf(__uint_as_float(r1[i]), sSc[c1], sSh[c1]), 0.f);
                    }
                    uint32_t hi32[32], lo32[32];
#pragma unroll
                    for (int p = 0; p < 32; p++) {
                        float a0 = v[2 * p], a1 = v[2 * p + 1];
                        hi32[p] = pack_bf16x2(a0, a1);
                        __nv_bfloat162 hb = *reinterpret_cast<__nv_bfloat162*>(&hi32[p]);
                        float2 hr = __bfloat1622float2(hb);
                        lo32[p] = pack_bf16x2(a0 - hr.x, a1 - hr.y);
                    }
                    STTM32(tmem + TM_A2HI + b0 * 16 + woff, hi32);
                    STTM32(tmem + TM_A2LO + b0 * 16 + woff, lo32);
                }
                TC_WAIT_ST();
                TC_FENCE_BEFORE();
            } else {
                // stage B2 chunks 2*half, 2*half+1 into A region buffers
#pragma unroll
                for (int it = 0; it < 8; it++) {
                    int idx = (t - 128) + it * 128;
                    int r = idx >> 3, kg = idx & 7;
                    uint32_t so = SW128((uint32_t)(r * 128 + kg * 16));
                    int c0 = 2 * half, c1 = 2 * half + 1;
                    CP_ASYNC16(sb + Q_A + so,         B2hi + (size_t)r * 256 + c0 * 64 + kg * 8);
                    CP_ASYNC16(sb + Q_A + 16384 + so, B2hi + (size_t)r * 256 + c1 * 64 + kg * 8);
                    CP_ASYNC16(sb + Q_A + 32768 + so, B2lo + (size_t)r * 256 + c0 * 64 + kg * 8);
                    CP_ASYNC16(sb + Q_A + 49152 + so, B2lo + (size_t)r * 256 + c1 * 64 + kg * 8);
                }
                CP_COMMIT();
                CP_WAIT0();
            }
            FENCE_ASYNC();
            __syncthreads();
            if (wid == 0 && elect_one()) {
                TC_FENCE_AFTER();
#pragma unroll
                for (int cc = 0; cc < 2; cc++) {
                    int c = 2 * half + cc;
                    uint32_t a_hi = tmem + TM_A2HI + c * 32;
                    uint32_t a_lo = tmem + TM_A2LO + c * 32;
                    uint64_t bh = make_desc(sb + Q_A + cc * 16384);
                    uint64_t bl = make_desc(sb + Q_A + 32768 + cc * 16384);
#pragma unroll
                    for (int s = 0; s < 4; s++)
                        mma_bf16_ts(tmem, a_hi + s * 8, bh + s * 2, TG_IDESC,
                                    (c == 0 && s == 0) ? 0u : 1u);
#pragma unroll
                    for (int s = 0; s < 4; s++)
                        mma_bf16_ts(tmem, a_hi + s * 8, bl + s * 2, TG_IDESC, 1u);
#pragma unroll
                    for (int s = 0; s < 4; s++)
                        mma_bf16_ts(tmem, a_lo + s * 8, bh + s * 2, TG_IDESC, 1u);
                }
                TC_COMMIT(sb + Q_MBAR);
            }
            MB_WAIT(sb + Q_MBAR, pc & 1); pc++;
            TC_FENCE_AFTER();
            __syncthreads();
        }

        // -------- final epilogue: h2 (tmem cols 0..127), 64-row statbuf --------
        for (int pr = 0; pr < 2; pr++) {
#pragma unroll
            for (int rh = 0; rh < 2; rh++) {
                if (wid < 4 && (wid >> 1) == rh) {
                    int rl = (wid & 1) * 32 + lid;
                    int grow = bm + rh * 64 + rl;
                    uint32_t r0[32], r1[32];
                    LDTM32(r0, tmem + pr * 64);
                    LDTM32(r1, tmem + pr * 64 + 32);
                    TC_WAIT_LD();
                    float v0[32], v1[32];
#pragma unroll
                    for (int i = 0; i < 32; i++) {
                        v0[i] = __uint_as_float(r0[i]) + sB[pr * 64 + i];
                        v1[i] = __uint_as_float(r1[i]) + sB[pr * 64 + 32 + i];
                    }
                    if (grow < M) {
                        float* cp = C + (size_t)grow * 128 + pr * 64;
#pragma unroll
                        for (int q = 0; q < 8; q++) {
                            *(float4*)(cp + q * 4)      = *(float4*)(v0 + q * 4);
                            *(float4*)(cp + 32 + q * 4) = *(float4*)(v1 + q * 4);
                        }
                    } else {
#pragma unroll
                        for (int i = 0; i < 32; i++) { v0[i] = 0.f; v1[i] = 0.f; }
                    }
#pragma unroll
                    for (int i = 0; i < 32; i++) {
                        statbuf[rl * 66 + i]      = v0[i];
                        statbuf[rl * 66 + 32 + i] = v1[i];
                    }
                }
                __syncthreads();
                {
                    int c = t & 63, h = t >> 6;
                    float s = 0.f, q = 0.f;
#pragma unroll 8
                    for (int rr = 0; rr < 16; rr++) {
                        float vv = statbuf[(h * 16 + rr) * 66 + c];
                        s += vv;
                        q = fmaf(vv, vv, q);
                    }
                    psum[h * 64 + c] = s;
                    psq[h * 64 + c]  = q;
                }
                __syncthreads();
                if (t < 64) {
                    float s4 = psum[t] + psum[64 + t] + psum[128 + t] + psum[192 + t];
                    float q4 = psq[t]  + psq[64 + t]  + psq[128 + t]  + psq[192 + t];
                    if (rh == 0) { ssl[pr * 64 + t] = s4;  sql[pr * 64 + t] = q4; }
                    else         { ssl[pr * 64 + t] += s4; sql[pr * 64 + t] += q4; }
                }
                __syncthreads();
            }
        }
        if (wid < 4) TC_FENCE_BEFORE();
        __syncthreads();
        if (t < 128) {
            atomicAdd(&g_ssum2[t], ssl[t]);
            atomicAdd(&g_ssq2[t],  sql[t]);
        }
        __syncthreads();
    }
#undef Q_STAGE_A

    if (t == 0) MB_INVAL(sb + Q_MBAR);
    if (wid == 0) TC_DEALLOC(tmem, 512);
}

// ---------------- readout pooling (computes outer BN inline) ----------------
__global__ void pool_k(const void* __restrict__ batch, int n,
                       const float* __restrict__ gamma, const float* __restrict__ beta,
                       float invM) {
    long long t = (long long)blockIdx.x * blockDim.x + threadIdx.x;
    long long i = t >> 5;
    if (i >= n) return;
    int lane = (int)(t & 31);
    long long g;
    if (g_i64flag) g = ((const long long*)batch)[i];
    else           g = (long long)((const int*)batch)[i];
    int c = lane * 4;
    float sc[4], sh[4];
#pragma unroll
    for (int j = 0; j < 4; j++) {
        float m   = g_ssum2[c + j] * invM;
        float var = g_ssq2[c + j] * invM - m * m;
        sc[j] = gamma[c + j] * rsqrtf(var + 1e-5f);
        sh[j] = beta[c + j] - m * sc[j];
    }
    float4 v = ((const float4*)g_h2)[i * 32 + lane];
    float r0 = fmaxf(fmaf(v.x, sc[0], sh[0]), 0.f);
    float r1 = fmaxf(fmaf(v.y, sc[1], sh[1]), 0.f);
    float r2 = fmaxf(fmaf(v.z, sc[2], sh[2]), 0.f);
    float r3 = fmaxf(fmaf(v.w, sc[3], sh[3]), 0.f);
    float* ps = g_ps + g * 128 + c;
    asm volatile("red.global.add.v4.f32 [%0], {%1, %2, %3, %4};"
                 :: "l"(ps), "f"(r0), "f"(r1), "f"(r2), "f"(r3) : "memory");
    unsigned int* mx = (unsigned int*)(g_pmx + g * 128 + c);
    atomicMax(mx + 0, __float_as_uint(r0));
    atomicMax(mx + 1, __float_as_uint(r1));
    atomicMax(mx + 2, __float_as_uint(r2));
    atomicMax(mx + 3, __float_as_uint(r3));
    if (lane == 0) atomicAdd(&g_cnt[g], 1.0f);
}

// ---------------- classifier ----------------
__global__ void cgemm1_k(const float* __restrict__ cW1, const float* __restrict__ cb1) {
    int g = blockIdx.x;
    int j = threadIdx.x;
    __shared__ float z[384];
    float cnt = fmaxf(g_cnt[g], 1.0f);
    float sv = g_ps[g * 128 + j];
    z[j]       = sv;
    z[128 + j] = sv / cnt;
    z[256 + j] = g_pmx[g * 128 + j];
    __syncthreads();
    float acc = cb1[j];
#pragma unroll 8
    for (int k = 0; k < 384; k++)
        acc = fmaf(z[k], cW1[k * 128 + j], acc);
    g_z1[g * 128 + j] = acc;
}

__global__ void cstats_k(const float* __restrict__ cg, const float* __restrict__ cbeta) {
    int j = threadIdx.x;
    float s = 0.f, q = 0.f;
    for (int g = 0; g < GCNT; g++) {
        float v = g_z1[g * 128 + j];
        s += v; q += v * v;
    }
    float m   = s * (1.0f / GCNT);
    float var = q * (1.0f / GCNT) - m * m;
    float sc  = cg[j] * rsqrtf(var + 1e-5f);
    g_scale[j] = sc;
    g_shift[j] = cbeta[j] - m * sc;
}

__global__ void chead_k(const float* __restrict__ cW2, const float* __restrict__ cb2,
                        const float* __restrict__ cW3, const float* __restrict__ cb3,
                        float* __restrict__ out) {
    int g = blockIdx.x;
    int j = threadIdx.x;
    __shared__ float a[128];
    __shared__ float z2[64];
    for (int k = j; k < 128; k += 64)
        a[k] = fmaxf(fmaf(g_z1[g * 128 + k], g_scale[k], g_shift[k]), 0.f);
    __syncthreads();
    float acc = cb2[j];
#pragma unroll 8
    for (int k = 0; k < 128; k++)
        acc = fmaf(a[k], cW2[k * 64 + j], acc);
    z2[j] = fmaxf(acc, 0.f);
    __syncthreads();
    if (j < 2) {
        float o = cb3[j];
#pragma unroll 8
        for (int k = 0; k < 64; k++)
            o = fmaf(z2[k], cW3[k * 2 + j], o);
        out[g * 2 + j] = o;
    }
}

// ---------------- launcher ----------------
extern "C" void kernel_launch(void* const* d_in, const int* in_sizes, int n_in,
                              void* d_out, int out_size) {
    const float* x     = (const float*)d_in[0];
    const void*  ei    = d_in[1];
    const void*  batch = d_in[2];
    int base = (in_sizes[3] == 1) ? 4 : 3;
    const float* W1    = (const float*)d_in[base + 0];
    const float* b1    = (const float*)d_in[base + 1];
    const float* g1    = (const float*)d_in[base + 2];
    const float* be1   = (const float*)d_in[base + 3];
    const float* W2    = (const float*)d_in[base + 4];
    const float* b2    = (const float*)d_in[base + 5];
    const float* gbn   = (const float*)d_in[base + 6];
    const float* bbn   = (const float*)d_in[base + 7];
    const float* eps   = (const float*)d_in[base + 8];
    const float* cW1   = (const float*)d_in[base + 9];
    const float* cb1   = (const float*)d_in[base + 10];
    const float* cg    = (const float*)d_in[base + 11];
    const float* cbeta = (const float*)d_in[base + 12];
    const float* cW2   = (const float*)d_in[base + 13];
    const float* cb2   = (const float*)d_in[base + 14];
    const float* cW3   = (const float*)d_in[base + 15];
    const float* cb3   = (const float*)d_in[base + 16];

    int n = in_sizes[0] / 128;
    long long E = (long long)in_sizes[1] / 2;
    int n32 = n * 32;
    int nb = (n32 + 255) / 256;
    int gx = (n + 127) / 128;
    int p1grid = (gx < 148) ? gx : 148;
    int p2grid = (gx < 148) ? gx : 148;
    int eblk = (int)((E + 255) / 256);
    int nscan = (n + 1023) / 1024;
    int ablk = (n * 32 + 255) / 256;
    float invM = 1.0f / (float)n;

    static int smem_set = 0;
    if (!smem_set) {
        cudaFuncSetAttribute(pass1_k, cudaFuncAttributeMaxDynamicSharedMemorySize, P1_SMEM);
        cudaFuncSetAttribute(pass2_k, cudaFuncAttributeMaxDynamicSharedMemorySize, Q_SMEM);
        smem_set = 1;
    }

    float *p_h2;
    uint8_t *p_ahi, *p_alo;
    __nv_bfloat16 *p_b1hi, *p_b1lo, *p_b2hi, *p_b2lo;
    cudaGetSymbolAddress((void**)&p_h2,  g_h2);
    cudaGetSymbolAddress((void**)&p_ahi, g_ahi);
    cudaGetSymbolAddress((void**)&p_alo, g_alo);
    cudaGetSymbolAddress((void**)&p_b1hi, g_b1hi);
    cudaGetSymbolAddress((void**)&p_b1lo, g_b1lo);
    cudaGetSymbolAddress((void**)&p_b2hi, g_b2hi);
    cudaGetSymbolAddress((void**)&p_b2lo, g_b2lo);

    detect_k<<<1, 1>>>((const unsigned int*)ei);
    wconv_k<<<(NLAYER * 256 * 128 + 255) / 256, 256>>>(W1, W2);
    zero_k<<<512, 256>>>(n, gx);

    count_k<<<eblk, 256>>>(ei, E);
    scanA_k<<<nscan, 256>>>(n);
    scanB_k<<<1, 32>>>(nscan);
    scanC_k<<<nscan, 256>>>(n);
    fill_k<<<eblk, 256>>>(ei, E);

    for (int l = 0; l < 4; l++) {
        if (l == 0)
            agg_k<false><<<ablk, 256>>>(x, eps, l, n, nullptr, nullptr, invM);
        else
            agg_k<true><<<ablk, 256>>>(p_h2, eps, l, n,
                                       gbn + (l - 1) * 128, bbn + (l - 1) * 128, invM);

        pass1_k<<<p1grid, 256, P1_SMEM>>>(
            p_ahi, p_alo,
            p_b1hi + (size_t)l * 32768, p_b1lo + (size_t)l * 32768, gx);
        pass2_k<<<p2grid, 256, Q_SMEM>>>(
            p_ahi, p_alo,
            p_b1hi + (size_t)l * 32768, p_b1lo + (size_t)l * 32768,
            p_b2hi + (size_t)l * 32768, p_b2lo + (size_t)l * 32768,
            b1 + l * 256, b2 + l * 128, g1 + l * 256, be1 + l * 256, invM,
            p_h2, n, gx);
    }

    pool_k<<<nb, 256>>>(batch, n, gbn + 3 * 128, bbn + 3 * 128, invM);
    cgemm1_k<<<GCNT, 128>>>(cW1, cb1);
    cstats_k<<<1, 128>>>(cg, cbeta);
    chead_k<<<GCNT, 64>>>(cW2, cb2, cW3, cb3, (float*)d_out);
}